// round 1
// baseline (speedup 1.0000x reference)
#include <cuda_runtime.h>
#include <math.h>

// Problem constants
#define BB 4
#define CC 256
#define NN_ 1024
#define HH 8
#define DD 256
#define HD 2048   // H*D

// Scratch (static __device__ arrays: allocation-free per harness rules)
__device__ float g_Q[(size_t)BB * HD * NN_];          // [B, H*D, N]
__device__ float g_K[(size_t)BB * HD * NN_];          // [B, H*D, N]
__device__ float g_V[(size_t)BB * HD * NN_];          // [B, H*DV, N]
__device__ float g_YP[(size_t)BB * CC * NN_];         // [B, DV, N]
__device__ float g_S[(size_t)BB * HH * NN_ * NN_];    // [B,H,N,N] energies -> probs (in place)

// ---------------------------------------------------------------------------
// NN GEMM: C[z][m][n] = sum_k A[m][k] * B[z][k][n] (+ bias[m])
// A shared across z (weights). Tiles: 64x64x16, 256 threads, 4x4 per thread.
// ---------------------------------------------------------------------------
__global__ void __launch_bounds__(256) gemm_nn_kernel(
    const float* __restrict__ A,    // [M, K] row-major
    const float* __restrict__ Bm,   // [K, Nd] per z
    const float* __restrict__ bias, // [M] or nullptr
    float* __restrict__ Cm,         // [M, Nd] per z
    int M, int Nd, int K,
    size_t strideB, size_t strideC)
{
    __shared__ float As[16][64];
    __shared__ float Bs[16][64];

    const int z = blockIdx.z;
    const float* Bz = Bm + (size_t)z * strideB;
    float* Cz = Cm + (size_t)z * strideC;

    const int m0 = blockIdx.y * 64;
    const int n0 = blockIdx.x * 64;
    const int tid = threadIdx.x;
    const int tx = tid & 15;
    const int ty = tid >> 4;

    // A loader: 64 rows(m) x 16 cols(k); one float4 per thread
    const int la_m = tid >> 2;
    const int la_k = (tid & 3) * 4;
    // B loader: 16 rows(k) x 64 cols(n)
    const int lb_k = tid >> 4;
    const int lb_n = (tid & 15) * 4;

    float acc[4][4] = {};

    for (int k0 = 0; k0 < K; k0 += 16) {
        float4 a4 = *reinterpret_cast<const float4*>(
            &A[(size_t)(m0 + la_m) * K + k0 + la_k]);
        As[la_k + 0][la_m] = a4.x;
        As[la_k + 1][la_m] = a4.y;
        As[la_k + 2][la_m] = a4.z;
        As[la_k + 3][la_m] = a4.w;

        *reinterpret_cast<float4*>(&Bs[lb_k][lb_n]) =
            *reinterpret_cast<const float4*>(
                &Bz[(size_t)(k0 + lb_k) * Nd + n0 + lb_n]);
        __syncthreads();

        #pragma unroll
        for (int k = 0; k < 16; k++) {
            float a[4], b[4];
            #pragma unroll
            for (int i = 0; i < 4; i++) a[i] = As[k][ty * 4 + i];
            #pragma unroll
            for (int j = 0; j < 4; j++) b[j] = Bs[k][tx * 4 + j];
            #pragma unroll
            for (int i = 0; i < 4; i++)
                #pragma unroll
                for (int j = 0; j < 4; j++)
                    acc[i][j] += a[i] * b[j];
        }
        __syncthreads();
    }

    #pragma unroll
    for (int i = 0; i < 4; i++) {
        int m = m0 + ty * 4 + i;
        float bv = bias ? bias[m] : 0.0f;
        #pragma unroll
        for (int j = 0; j < 4; j++)
            Cz[(size_t)m * Nd + n0 + tx * 4 + j] = acc[i][j] + bv;
    }
}

// ---------------------------------------------------------------------------
// TN GEMM: C[z][m][n] = sum_k A[z][k][m] * B[z][k][n]
// Used for S = Q^T K (per (b,h) slice). Both operand tiles are k-major:
// direct float4 stores, no transpose in smem.
// ---------------------------------------------------------------------------
__global__ void __launch_bounds__(256) gemm_tn_kernel(
    const float* __restrict__ A,  // [K, M] per z (row stride = M)
    const float* __restrict__ Bm, // [K, Nd] per z (row stride = Nd)
    float* __restrict__ Cm,       // [M, Nd] per z
    int M, int Nd, int K,
    size_t strideA, size_t strideB, size_t strideC)
{
    __shared__ float As[16][64];
    __shared__ float Bs[16][64];

    const int z = blockIdx.z;
    const float* Az = A + (size_t)z * strideA;
    const float* Bz = Bm + (size_t)z * strideB;
    float* Cz = Cm + (size_t)z * strideC;

    const int m0 = blockIdx.y * 64;
    const int n0 = blockIdx.x * 64;
    const int tid = threadIdx.x;
    const int tx = tid & 15;
    const int ty = tid >> 4;

    const int lk = tid >> 4;        // 0..15
    const int lm = (tid & 15) * 4;  // 0..60

    float acc[4][4] = {};

    for (int k0 = 0; k0 < K; k0 += 16) {
        *reinterpret_cast<float4*>(&As[lk][lm]) =
            *reinterpret_cast<const float4*>(
                &Az[(size_t)(k0 + lk) * M + m0 + lm]);
        *reinterpret_cast<float4*>(&Bs[lk][lm]) =
            *reinterpret_cast<const float4*>(
                &Bz[(size_t)(k0 + lk) * Nd + n0 + lm]);
        __syncthreads();

        #pragma unroll
        for (int k = 0; k < 16; k++) {
            float a[4], b[4];
            #pragma unroll
            for (int i = 0; i < 4; i++) a[i] = As[k][ty * 4 + i];
            #pragma unroll
            for (int j = 0; j < 4; j++) b[j] = Bs[k][tx * 4 + j];
            #pragma unroll
            for (int i = 0; i < 4; i++)
                #pragma unroll
                for (int j = 0; j < 4; j++)
                    acc[i][j] += a[i] * b[j];
        }
        __syncthreads();
    }

    #pragma unroll
    for (int i = 0; i < 4; i++) {
        int m = m0 + ty * 4 + i;
        #pragma unroll
        for (int j = 0; j < 4; j++)
            Cz[(size_t)m * Nd + n0 + tx * 4 + j] = acc[i][j];
    }
}

// ---------------------------------------------------------------------------
// Row softmax over the last dim (1024) of S, in place. One block per row.
// ---------------------------------------------------------------------------
__global__ void __launch_bounds__(256) softmax_kernel(float* __restrict__ S)
{
    __shared__ float red[256];
    float* r = S + (size_t)blockIdx.x * NN_;
    const int tid = threadIdx.x;

    float v[4];
    float mx = -INFINITY;
    #pragma unroll
    for (int j = 0; j < 4; j++) {
        v[j] = r[tid + j * 256];
        mx = fmaxf(mx, v[j]);
    }
    red[tid] = mx;
    __syncthreads();
    for (int s = 128; s > 0; s >>= 1) {
        if (tid < s) red[tid] = fmaxf(red[tid], red[tid + s]);
        __syncthreads();
    }
    mx = red[0];
    __syncthreads();

    float sum = 0.0f;
    #pragma unroll
    for (int j = 0; j < 4; j++) {
        v[j] = __expf(v[j] - mx);
        sum += v[j];
    }
    red[tid] = sum;
    __syncthreads();
    for (int s = 128; s > 0; s >>= 1) {
        if (tid < s) red[tid] += red[tid + s];
        __syncthreads();
    }
    float inv = 1.0f / red[0];

    #pragma unroll
    for (int j = 0; j < 4; j++)
        r[tid + j * 256] = v[j] * inv;
}

// ---------------------------------------------------------------------------
// NT GEMM + epilogue: O[z][d][n] = sum_m V[z][d][m] * P[z][n][m]
// out[b][h*DD+d][n] = (g*O + yp[b][d][n]) / (1+g),  z = b*H + h
// ---------------------------------------------------------------------------
__global__ void __launch_bounds__(256) gemm_o_kernel(
    const float* __restrict__ V,   // [B*H, D, N] (per-z slice [D, K=N])
    const float* __restrict__ P,   // [B*H, N, N] (per-z slice [Nq, K=N])
    const float* __restrict__ YP,  // [B, DV, N]
    const float* __restrict__ gamma, // [H]
    float* __restrict__ out)       // [B, H*DV, N]
{
    __shared__ float As[16][64];
    __shared__ float Bs[16][64];

    const int z = blockIdx.z;
    const int b = z >> 3;       // /H
    const int h = z & 7;        // %H
    const float* Az = V + (size_t)z * DD * NN_;
    const float* Bz = P + (size_t)z * NN_ * NN_;

    const int m0 = blockIdx.y * 64;   // d
    const int n0 = blockIdx.x * 64;   // query n
    const int tid = threadIdx.x;
    const int tx = tid & 15;
    const int ty = tid >> 4;

    const int lr = tid >> 2;        // row (m or n), 0..63
    const int lk = (tid & 3) * 4;   // k within tile

    float acc[4][4] = {};

    for (int k0 = 0; k0 < NN_; k0 += 16) {
        float4 a4 = *reinterpret_cast<const float4*>(
            &Az[(size_t)(m0 + lr) * NN_ + k0 + lk]);
        As[lk + 0][lr] = a4.x;
        As[lk + 1][lr] = a4.y;
        As[lk + 2][lr] = a4.z;
        As[lk + 3][lr] = a4.w;

        float4 b4 = *reinterpret_cast<const float4*>(
            &Bz[(size_t)(n0 + lr) * NN_ + k0 + lk]);
        Bs[lk + 0][lr] = b4.x;
        Bs[lk + 1][lr] = b4.y;
        Bs[lk + 2][lr] = b4.z;
        Bs[lk + 3][lr] = b4.w;
        __syncthreads();

        #pragma unroll
        for (int k = 0; k < 16; k++) {
            float a[4], bqv[4];
            #pragma unroll
            for (int i = 0; i < 4; i++) a[i] = As[k][ty * 4 + i];
            #pragma unroll
            for (int j = 0; j < 4; j++) bqv[j] = Bs[k][tx * 4 + j];
            #pragma unroll
            for (int i = 0; i < 4; i++)
                #pragma unroll
                for (int j = 0; j < 4; j++)
                    acc[i][j] += a[i] * bqv[j];
        }
        __syncthreads();
    }

    const float g = gamma[h];
    const float inv1pg = 1.0f / (1.0f + g);
    #pragma unroll
    for (int i = 0; i < 4; i++) {
        int d = m0 + ty * 4 + i;
        #pragma unroll
        for (int j = 0; j < 4; j++) {
            int n = n0 + tx * 4 + j;
            float yp = YP[((size_t)b * CC + d) * NN_ + n];
            out[((size_t)b * HD + h * DD + d) * NN_ + n] =
                (g * acc[i][j] + yp) * inv1pg;
        }
    }
}

// ---------------------------------------------------------------------------
extern "C" void kernel_launch(void* const* d_in, const int* in_sizes, int n_in,
                              void* d_out, int out_size)
{
    const float* x     = (const float*)d_in[0];
    const float* y     = (const float*)d_in[1];
    const float* Wq    = (const float*)d_in[2];
    const float* bq    = (const float*)d_in[3];
    const float* Wk    = (const float*)d_in[4];
    const float* bk    = (const float*)d_in[5];
    const float* Wv    = (const float*)d_in[6];
    const float* bv    = (const float*)d_in[7];
    const float* Wp    = (const float*)d_in[8];
    const float* gamma = (const float*)d_in[9];
    float* out = (float*)d_out;

    float *Q, *K, *V, *YP, *S;
    cudaGetSymbolAddress((void**)&Q,  g_Q);
    cudaGetSymbolAddress((void**)&K,  g_K);
    cudaGetSymbolAddress((void**)&V,  g_V);
    cudaGetSymbolAddress((void**)&YP, g_YP);
    cudaGetSymbolAddress((void**)&S,  g_S);

    dim3 t(256);

    // Projections: per-batch GEMMs [M x 256] * [256 x 1024]
    gemm_nn_kernel<<<dim3(16, 32, BB), t>>>(
        Wq, x, bq, Q, HD, NN_, CC, (size_t)CC * NN_, (size_t)HD * NN_);
    gemm_nn_kernel<<<dim3(16, 32, BB), t>>>(
        Wk, x, bk, K, HD, NN_, CC, (size_t)CC * NN_, (size_t)HD * NN_);
    gemm_nn_kernel<<<dim3(16, 32, BB), t>>>(
        Wv, y, bv, V, HD, NN_, CC, (size_t)CC * NN_, (size_t)HD * NN_);
    gemm_nn_kernel<<<dim3(16, 4, BB), t>>>(
        Wp, y, nullptr, YP, CC, NN_, CC, (size_t)CC * NN_, (size_t)CC * NN_);

    // S = Q^T K per (b,h): [1024 x 256]^T-style TN GEMM -> [1024 x 1024]
    gemm_tn_kernel<<<dim3(16, 16, BB * HH), t>>>(
        Q, K, S, NN_, NN_, DD,
        (size_t)DD * NN_, (size_t)DD * NN_, (size_t)NN_ * NN_);

    // Softmax over keys (rows of length 1024), in place
    softmax_kernel<<<BB * HH * NN_, 256>>>(S);

    // O = V * P^T per (b,h), fused gamma/residual epilogue -> out
    gemm_o_kernel<<<dim3(16, 4, BB * HH), t>>>(V, S, YP, gamma, out);
}

// round 3
// speedup vs baseline: 1.5853x; 1.5853x over previous
#include <cuda_runtime.h>
#include <cuda_bf16.h>
#include <math.h>
#include <stdint.h>

// Problem constants
#define BB 4
#define CC 256
#define NN_ 1024
#define HH 8
#define DD 256
#define HD 2048
#define ZZ 32   // B*H

// GEMM tiling
#define BM 128
#define BN 64
#define BK 32
#define LDA 40          // padded row length in bf16 elems (80 B)

// ---------------- scratch (__device__ globals: allocation-free) -------------
__device__ float g_Q[(size_t)BB * HD * NN_];
__device__ float g_K[(size_t)BB * HD * NN_];
__device__ float g_V[(size_t)BB * HD * NN_];
__device__ float g_YP[(size_t)BB * CC * NN_];
__device__ float g_S[(size_t)ZZ * NN_ * NN_];

__device__ __nv_bfloat16 g_Qth[(size_t)ZZ * NN_ * DD];
__device__ __nv_bfloat16 g_Qtl[(size_t)ZZ * NN_ * DD];
__device__ __nv_bfloat16 g_Kth[(size_t)ZZ * NN_ * DD];
__device__ __nv_bfloat16 g_Ktl[(size_t)ZZ * NN_ * DD];
__device__ __nv_bfloat16 g_Vh[(size_t)BB * HD * NN_];
__device__ __nv_bfloat16 g_Vl[(size_t)BB * HD * NN_];
__device__ __nv_bfloat16 g_Ph[(size_t)ZZ * NN_ * NN_];
__device__ __nv_bfloat16 g_Pl[(size_t)ZZ * NN_ * NN_];

// ---------------- helpers ---------------------------------------------------
__device__ __forceinline__ uint32_t smem_u32(const void* p) {
    uint32_t a;
    asm("{ .reg .u64 t; cvta.to.shared.u64 t, %1; cvt.u32.u64 %0, t; }"
        : "=r"(a) : "l"(p));
    return a;
}
__device__ __forceinline__ void ldsm_x4(uint32_t* r, uint32_t addr) {
    asm volatile("ldmatrix.sync.aligned.m8n8.x4.shared.b16 {%0,%1,%2,%3}, [%4];"
                 : "=r"(r[0]), "=r"(r[1]), "=r"(r[2]), "=r"(r[3]) : "r"(addr));
}
__device__ __forceinline__ void mma_bf16(float* c, const uint32_t* a, const uint32_t* b) {
    asm volatile(
        "mma.sync.aligned.m16n8k16.row.col.f32.bf16.bf16.f32 "
        "{%0,%1,%2,%3}, {%4,%5,%6,%7}, {%8,%9}, {%0,%1,%2,%3};"
        : "+f"(c[0]), "+f"(c[1]), "+f"(c[2]), "+f"(c[3])
        : "r"(a[0]), "r"(a[1]), "r"(a[2]), "r"(a[3]), "r"(b[0]), "r"(b[1]));
}

// ---------------------------------------------------------------------------
// Shared TN mma.sync mainloop:
//   acc[mt][nt][4] += A[i][k] * B[j][k]  (A: BMxK rows i, B: BNxK rows j)
//   3x bf16 split: Ah*Bh + Ah*Bl + Al*Bh
// ---------------------------------------------------------------------------
__device__ __forceinline__ void mma_mainloop(
    const __nv_bfloat16* __restrict__ gAh, const __nv_bfloat16* __restrict__ gAl,
    size_t strideA,
    const __nv_bfloat16* __restrict__ gBh, const __nv_bfloat16* __restrict__ gBl,
    size_t strideB,
    int KTOT,
    __nv_bfloat16* smAh, __nv_bfloat16* smAl,
    __nv_bfloat16* smBh, __nv_bfloat16* smBl,
    float acc[2][4][4])
{
    const int tid = threadIdx.x;
    const int lane = tid & 31, wid = tid >> 5;
    const int wm = (wid & 3) * 32;        // warp m origin (0..96)
    const int wn = (wid >> 2) * 32;       // warp n origin (0/32)
    const int r = tid >> 2, q = tid & 3;  // loader row / 16B chunk

    const uint32_t baseAh = smem_u32(smAh), baseAl = smem_u32(smAl);
    const uint32_t baseBh = smem_u32(smBh), baseBl = smem_u32(smBl);

    // ldmatrix per-lane coordinates
    const int a_row = lane & 15;
    const int a_col = (lane >> 4) * 8;
    const int b_row = (lane & 7) + (lane >> 4) * 8;
    const int b_col = ((lane >> 3) & 1) * 8;

    uint4 pA0h, pA1h, pA0l, pA1l, pB0h, pB0l;
    // prefetch k0 = 0
    pA0h = *reinterpret_cast<const uint4*>(gAh + (size_t)r * strideA + q * 8);
    pA1h = *reinterpret_cast<const uint4*>(gAh + (size_t)(r + 64) * strideA + q * 8);
    pA0l = *reinterpret_cast<const uint4*>(gAl + (size_t)r * strideA + q * 8);
    pA1l = *reinterpret_cast<const uint4*>(gAl + (size_t)(r + 64) * strideA + q * 8);
    pB0h = *reinterpret_cast<const uint4*>(gBh + (size_t)r * strideB + q * 8);
    pB0l = *reinterpret_cast<const uint4*>(gBl + (size_t)r * strideB + q * 8);

    for (int k0 = 0; k0 < KTOT; k0 += BK) {
        *reinterpret_cast<uint4*>(smAh + r * LDA + q * 8) = pA0h;
        *reinterpret_cast<uint4*>(smAh + (r + 64) * LDA + q * 8) = pA1h;
        *reinterpret_cast<uint4*>(smAl + r * LDA + q * 8) = pA0l;
        *reinterpret_cast<uint4*>(smAl + (r + 64) * LDA + q * 8) = pA1l;
        *reinterpret_cast<uint4*>(smBh + r * LDA + q * 8) = pB0h;
        *reinterpret_cast<uint4*>(smBl + r * LDA + q * 8) = pB0l;
        __syncthreads();

        if (k0 + BK < KTOT) {
            int kn = k0 + BK;
            pA0h = *reinterpret_cast<const uint4*>(gAh + (size_t)r * strideA + kn + q * 8);
            pA1h = *reinterpret_cast<const uint4*>(gAh + (size_t)(r + 64) * strideA + kn + q * 8);
            pA0l = *reinterpret_cast<const uint4*>(gAl + (size_t)r * strideA + kn + q * 8);
            pA1l = *reinterpret_cast<const uint4*>(gAl + (size_t)(r + 64) * strideA + kn + q * 8);
            pB0h = *reinterpret_cast<const uint4*>(gBh + (size_t)r * strideB + kn + q * 8);
            pB0l = *reinterpret_cast<const uint4*>(gBl + (size_t)r * strideB + kn + q * 8);
        }

#pragma unroll
        for (int kk = 0; kk < BK; kk += 16) {
            uint32_t ah[2][4], al[2][4], bh[2][4], bl[2][4];
#pragma unroll
            for (int mt = 0; mt < 2; mt++) {
                uint32_t ra = (uint32_t)(((wm + mt * 16 + a_row) * LDA + kk + a_col) * 2);
                ldsm_x4(ah[mt], baseAh + ra);
                ldsm_x4(al[mt], baseAl + ra);
            }
#pragma unroll
            for (int g = 0; g < 2; g++) {
                uint32_t rb = (uint32_t)(((wn + g * 16 + b_row) * LDA + kk + b_col) * 2);
                ldsm_x4(bh[g], baseBh + rb);
                ldsm_x4(bl[g], baseBl + rb);
            }
#pragma unroll
            for (int mt = 0; mt < 2; mt++)
#pragma unroll
                for (int nt = 0; nt < 4; nt++) {
                    int g = nt >> 1, u = (nt & 1) * 2;
                    mma_bf16(acc[mt][nt], ah[mt], &bh[g][u]);
                    mma_bf16(acc[mt][nt], ah[mt], &bl[g][u]);
                    mma_bf16(acc[mt][nt], al[mt], &bh[g][u]);
                }
        }
        __syncthreads();
    }
}

// ---------------------------------------------------------------------------
// S = Q^T K : grid (16 jTiles, 8 iTiles, 32 z), 256 threads
// ---------------------------------------------------------------------------
__global__ void __launch_bounds__(256) attn_s_kernel(
    const __nv_bfloat16* __restrict__ Qh, const __nv_bfloat16* __restrict__ Ql,
    const __nv_bfloat16* __restrict__ Kh, const __nv_bfloat16* __restrict__ Kl,
    float* __restrict__ S)
{
    __shared__ __nv_bfloat16 smAh[BM * LDA], smAl[BM * LDA];
    __shared__ __nv_bfloat16 smBh[BN * LDA], smBl[BN * LDA];

    const int z = blockIdx.z;
    const int i0 = blockIdx.y * BM, j0 = blockIdx.x * BN;

    float acc[2][4][4] = {};
    mma_mainloop(Qh + ((size_t)z * NN_ + i0) * DD, Ql + ((size_t)z * NN_ + i0) * DD, DD,
                 Kh + ((size_t)z * NN_ + j0) * DD, Kl + ((size_t)z * NN_ + j0) * DD, DD,
                 DD, smAh, smAl, smBh, smBl, acc);

    const int lane = threadIdx.x & 31, wid = threadIdx.x >> 5;
    const int wm = (wid & 3) * 32, wn = (wid >> 2) * 32;
#pragma unroll
    for (int mt = 0; mt < 2; mt++)
#pragma unroll
        for (int nt = 0; nt < 4; nt++) {
            int i = i0 + wm + mt * 16 + (lane >> 2);
            int j = j0 + wn + nt * 8 + 2 * (lane & 3);
            float* p0 = &S[((size_t)z * NN_ + i) * NN_ + j];
            float* p1 = &S[((size_t)z * NN_ + i + 8) * NN_ + j];
            *reinterpret_cast<float2*>(p0) = make_float2(acc[mt][nt][0], acc[mt][nt][1]);
            *reinterpret_cast<float2*>(p1) = make_float2(acc[mt][nt][2], acc[mt][nt][3]);
        }
}

// ---------------------------------------------------------------------------
// O = P V^T + epilogue : grid (4 dTiles, 8 iTiles, 32 z), 256 threads
// ---------------------------------------------------------------------------
__global__ void __launch_bounds__(256) attn_o_kernel(
    const __nv_bfloat16* __restrict__ Ph, const __nv_bfloat16* __restrict__ Pl,
    const __nv_bfloat16* __restrict__ Vh, const __nv_bfloat16* __restrict__ Vl,
    const float* __restrict__ YP, const float* __restrict__ gamma,
    float* __restrict__ out)
{
    __shared__ __nv_bfloat16 smAh[BM * LDA], smAl[BM * LDA];
    __shared__ __nv_bfloat16 smBh[BN * LDA], smBl[BN * LDA];

    const int z = blockIdx.z, b = z >> 3, h = z & 7;
    const int i0 = blockIdx.y * BM, d0 = blockIdx.x * BN;

    float acc[2][4][4] = {};
    mma_mainloop(Ph + ((size_t)z * NN_ + i0) * NN_, Pl + ((size_t)z * NN_ + i0) * NN_, NN_,
                 Vh + ((size_t)b * HD + h * DD + d0) * NN_,
                 Vl + ((size_t)b * HD + h * DD + d0) * NN_, NN_,
                 NN_, smAh, smAl, smBh, smBl, acc);

    const int lane = threadIdx.x & 31, wid = threadIdx.x >> 5;
    const int wm = (wid & 3) * 32, wn = (wid >> 2) * 32;
    const float g = gamma[h];
    const float inv1pg = 1.0f / (1.0f + g);

#pragma unroll
    for (int mt = 0; mt < 2; mt++)
#pragma unroll
        for (int nt = 0; nt < 4; nt++) {
            int i = i0 + wm + mt * 16 + (lane >> 2);
            int d = d0 + wn + nt * 8 + 2 * (lane & 3);
#pragma unroll
            for (int u = 0; u < 4; u++) {
                int dd = d + (u & 1);
                int ii = i + (u >> 1) * 8;
                float yp = YP[((size_t)b * CC + dd) * NN_ + ii];
                out[((size_t)b * HD + h * DD + dd) * NN_ + ii] =
                    (g * acc[mt][nt][u] + yp) * inv1pg;
            }
        }
}

// ---------------------------------------------------------------------------
// SIMT NN GEMM for projections
// ---------------------------------------------------------------------------
__global__ void __launch_bounds__(256) gemm_nn_kernel(
    const float* __restrict__ A, const float* __restrict__ Bm,
    const float* __restrict__ bias, float* __restrict__ Cm,
    int M, int Nd, int Kd, size_t strideB, size_t strideC)
{
    __shared__ float As[16][64];
    __shared__ float Bs[16][64];
    const int z = blockIdx.z;
    const float* Bz = Bm + (size_t)z * strideB;
    float* Cz = Cm + (size_t)z * strideC;
    const int m0 = blockIdx.y * 64, n0 = blockIdx.x * 64;
    const int tid = threadIdx.x, tx = tid & 15, ty = tid >> 4;
    const int la_m = tid >> 2, la_k = (tid & 3) * 4;
    const int lb_k = tid >> 4, lb_n = (tid & 15) * 4;
    float acc[4][4] = {};
    for (int k0 = 0; k0 < Kd; k0 += 16) {
        float4 a4 = *reinterpret_cast<const float4*>(&A[(size_t)(m0 + la_m) * Kd + k0 + la_k]);
        As[la_k + 0][la_m] = a4.x; As[la_k + 1][la_m] = a4.y;
        As[la_k + 2][la_m] = a4.z; As[la_k + 3][la_m] = a4.w;
        *reinterpret_cast<float4*>(&Bs[lb_k][lb_n]) =
            *reinterpret_cast<const float4*>(&Bz[(size_t)(k0 + lb_k) * Nd + n0 + lb_n]);
        __syncthreads();
#pragma unroll
        for (int k = 0; k < 16; k++) {
            float a[4], bv[4];
#pragma unroll
            for (int i = 0; i < 4; i++) a[i] = As[k][ty * 4 + i];
#pragma unroll
            for (int j = 0; j < 4; j++) bv[j] = Bs[k][tx * 4 + j];
#pragma unroll
            for (int i = 0; i < 4; i++)
#pragma unroll
                for (int j = 0; j < 4; j++) acc[i][j] += a[i] * bv[j];
        }
        __syncthreads();
    }
#pragma unroll
    for (int i = 0; i < 4; i++) {
        int m = m0 + ty * 4 + i;
        float bv = bias ? bias[m] : 0.0f;
#pragma unroll
        for (int j = 0; j < 4; j++)
            Cz[(size_t)m * Nd + n0 + tx * 4 + j] = acc[i][j] + bv;
    }
}

// ---------------------------------------------------------------------------
// Transpose+split: [B][2048][1024] fp32 (b,h) slice -> [z][n][d] bf16 hi/lo
// ---------------------------------------------------------------------------
__global__ void __launch_bounds__(256) transpose_split_kernel(
    const float* __restrict__ in,
    __nv_bfloat16* __restrict__ oh, __nv_bfloat16* __restrict__ ol)
{
    __shared__ float t[32][33];
    const int z = blockIdx.z, b = z >> 3, h = z & 7;
    const int n0 = blockIdx.x * 32, d0 = blockIdx.y * 32;
    const int tx = threadIdx.x, ty = threadIdx.y;
    for (int r = ty; r < 32; r += 8)
        t[r][tx] = in[((size_t)b * HD + h * DD + d0 + r) * NN_ + n0 + tx];
    __syncthreads();
    for (int r = ty; r < 32; r += 8) {
        float v = t[tx][r];
        __nv_bfloat16 hi = __float2bfloat16(v);
        float lo = v - __bfloat162float(hi);
        size_t o = ((size_t)z * NN_ + n0 + r) * DD + d0 + tx;
        oh[o] = hi;
        ol[o] = __float2bfloat16(lo);
    }
}

__global__ void __launch_bounds__(256) split_kernel(
    const float* __restrict__ in,
    __nv_bfloat16* __restrict__ oh, __nv_bfloat16* __restrict__ ol, size_t n)
{
    size_t i = (size_t)blockIdx.x * blockDim.x + threadIdx.x;
    if (i < n) {
        float v = in[i];
        __nv_bfloat16 hi = __float2bfloat16(v);
        oh[i] = hi;
        ol[i] = __float2bfloat16(v - __bfloat162float(hi));
    }
}

// ---------------------------------------------------------------------------
// Row softmax over keys, emit bf16 hi/lo
// ---------------------------------------------------------------------------
__global__ void __launch_bounds__(256) softmax_kernel(
    const float* __restrict__ S,
    __nv_bfloat16* __restrict__ Ph, __nv_bfloat16* __restrict__ Pl)
{
    __shared__ float red[256];
    const size_t row = blockIdx.x;
    const float* r = S + row * NN_;
    const int tid = threadIdx.x;

    float v[4];
    float mx = -INFINITY;
#pragma unroll
    for (int j = 0; j < 4; j++) { v[j] = r[tid + j * 256]; mx = fmaxf(mx, v[j]); }
    red[tid] = mx;
    __syncthreads();
    for (int s = 128; s > 0; s >>= 1) {
        if (tid < s) red[tid] = fmaxf(red[tid], red[tid + s]);
        __syncthreads();
    }
    mx = red[0];
    __syncthreads();

    float sum = 0.0f;
#pragma unroll
    for (int j = 0; j < 4; j++) { v[j] = __expf(v[j] - mx); sum += v[j]; }
    red[tid] = sum;
    __syncthreads();
    for (int s = 128; s > 0; s >>= 1) {
        if (tid < s) red[tid] += red[tid + s];
        __syncthreads();
    }
    float inv = 1.0f / red[0];

#pragma unroll
    for (int j = 0; j < 4; j++) {
        float p = v[j] * inv;
        __nv_bfloat16 hi = __float2bfloat16(p);
        size_t o = row * NN_ + tid + j * 256;
        Ph[o] = hi;
        Pl[o] = __float2bfloat16(p - __bfloat162float(hi));
    }
}

// ---------------------------------------------------------------------------
extern "C" void kernel_launch(void* const* d_in, const int* in_sizes, int n_in,
                              void* d_out, int out_size)
{
    const float* x     = (const float*)d_in[0];
    const float* y     = (const float*)d_in[1];
    const float* Wq    = (const float*)d_in[2];
    const float* bq    = (const float*)d_in[3];
    const float* Wk    = (const float*)d_in[4];
    const float* bk    = (const float*)d_in[5];
    const float* Wv    = (const float*)d_in[6];
    const float* bv    = (const float*)d_in[7];
    const float* Wp    = (const float*)d_in[8];
    const float* gamma = (const float*)d_in[9];
    float* out = (float*)d_out;

    float *Q, *K, *V, *YP, *S;
    __nv_bfloat16 *Qth, *Qtl, *Kth, *Ktl, *Vh, *Vl, *Ph, *Pl;
    cudaGetSymbolAddress((void**)&Q,   g_Q);
    cudaGetSymbolAddress((void**)&K,   g_K);
    cudaGetSymbolAddress((void**)&V,   g_V);
    cudaGetSymbolAddress((void**)&YP,  g_YP);
    cudaGetSymbolAddress((void**)&S,   g_S);
    cudaGetSymbolAddress((void**)&Qth, g_Qth);
    cudaGetSymbolAddress((void**)&Qtl, g_Qtl);
    cudaGetSymbolAddress((void**)&Kth, g_Kth);
    cudaGetSymbolAddress((void**)&Ktl, g_Ktl);
    cudaGetSymbolAddress((void**)&Vh,  g_Vh);
    cudaGetSymbolAddress((void**)&Vl,  g_Vl);
    cudaGetSymbolAddress((void**)&Ph,  g_Ph);
    cudaGetSymbolAddress((void**)&Pl,  g_Pl);

    dim3 t(256);

    // Projections (SIMT fp32)
    gemm_nn_kernel<<<dim3(16, 32, BB), t>>>(Wq, x, bq, Q, HD, NN_, CC,
                                            (size_t)CC * NN_, (size_t)HD * NN_);
    gemm_nn_kernel<<<dim3(16, 32, BB), t>>>(Wk, x, bk, K, HD, NN_, CC,
                                            (size_t)CC * NN_, (size_t)HD * NN_);
    gemm_nn_kernel<<<dim3(16, 32, BB), t>>>(Wv, y, bv, V, HD, NN_, CC,
                                            (size_t)CC * NN_, (size_t)HD * NN_);
    gemm_nn_kernel<<<dim3(16, 4, BB), t>>>(Wp, y, nullptr, YP, CC, NN_, CC,
                                           (size_t)CC * NN_, (size_t)CC * NN_);

    // Split / transpose into bf16 hi/lo
    transpose_split_kernel<<<dim3(32, 8, ZZ), dim3(32, 8)>>>(Q, Qth, Qtl);
    transpose_split_kernel<<<dim3(32, 8, ZZ), dim3(32, 8)>>>(K, Kth, Ktl);
    {
        size_t n = (size_t)BB * HD * NN_;
        split_kernel<<<(unsigned)((n + 255) / 256), t>>>(V, Vh, Vl, n);
    }

    // S = Q^T K (mma.sync bf16 3x-split)
    attn_s_kernel<<<dim3(16, 8, ZZ), t>>>(Qth, Qtl, Kth, Ktl, S);

    // softmax -> P hi/lo
    softmax_kernel<<<ZZ * NN_, t>>>(S, Ph, Pl);

    // O = P V^T + epilogue (mma.sync bf16 3x-split)
    attn_o_kernel<<<dim3(4, 8, ZZ), t>>>(Ph, Pl, Vh, Vl, YP, gamma, out);
}

// round 5
// speedup vs baseline: 1.6163x; 1.0195x over previous
#include <cuda_runtime.h>
#include <cuda_bf16.h>
#include <math.h>
#include <stdint.h>

// Problem constants
#define BB 4
#define CC 256
#define NN_ 1024
#define HH 8
#define DD 256
#define HD 2048
#define ZZ 32   // B*H

// Attention GEMM tiling
#define BM 128
#define BN 128
#define BK 32
#define LDA 40                 // padded row length (bf16 elems) = 80 B
#define TILE_E (128 * LDA)     // elems per operand tile
#define STAGE_E (4 * TILE_E)   // Ah, Al, Bh, Bl
#define SMEM_BYTES (2 * STAGE_E * 2)   // 2 stages * bytes

// ---------------- scratch (__device__ globals: allocation-free) -------------
__device__ __align__(256) float g_Q[(size_t)BB * HD * NN_];
__device__ __align__(256) float g_K[(size_t)BB * HD * NN_];
__device__ __align__(256) float g_V[(size_t)BB * HD * NN_];
__device__ __align__(256) float g_YP[(size_t)BB * CC * NN_];
__device__ __align__(256) float g_S[(size_t)ZZ * NN_ * NN_];

__device__ __align__(256) __nv_bfloat16 g_Qth[(size_t)ZZ * NN_ * DD];
__device__ __align__(256) __nv_bfloat16 g_Qtl[(size_t)ZZ * NN_ * DD];
__device__ __align__(256) __nv_bfloat16 g_Kth[(size_t)ZZ * NN_ * DD];
__device__ __align__(256) __nv_bfloat16 g_Ktl[(size_t)ZZ * NN_ * DD];
__device__ __align__(256) __nv_bfloat16 g_Vh[(size_t)BB * HD * NN_];
__device__ __align__(256) __nv_bfloat16 g_Vl[(size_t)BB * HD * NN_];
__device__ __align__(256) __nv_bfloat16 g_Ph[(size_t)ZZ * NN_ * NN_];
__device__ __align__(256) __nv_bfloat16 g_Pl[(size_t)ZZ * NN_ * NN_];

// ---------------- helpers ---------------------------------------------------
__device__ __forceinline__ uint32_t smem_u32(const void* p) {
    uint32_t a;
    asm("{ .reg .u64 t; cvta.to.shared.u64 t, %1; cvt.u32.u64 %0, t; }"
        : "=r"(a) : "l"(p));
    return a;
}
__device__ __forceinline__ void ldsm_x4(uint32_t* r, uint32_t addr) {
    asm volatile("ldmatrix.sync.aligned.m8n8.x4.shared.b16 {%0,%1,%2,%3}, [%4];"
                 : "=r"(r[0]), "=r"(r[1]), "=r"(r[2]), "=r"(r[3]) : "r"(addr));
}
__device__ __forceinline__ void mma_bf16(float* c, const uint32_t* a, const uint32_t* b) {
    asm volatile(
        "mma.sync.aligned.m16n8k16.row.col.f32.bf16.bf16.f32 "
        "{%0,%1,%2,%3}, {%4,%5,%6,%7}, {%8,%9}, {%0,%1,%2,%3};"
        : "+f"(c[0]), "+f"(c[1]), "+f"(c[2]), "+f"(c[3])
        : "r"(a[0]), "r"(a[1]), "r"(a[2]), "r"(a[3]), "r"(b[0]), "r"(b[1]));
}
__device__ __forceinline__ void cp_async16(uint32_t sm, const void* g) {
    asm volatile("cp.async.cg.shared.global [%0], [%1], 16;" :: "r"(sm), "l"(g));
}
__device__ __forceinline__ void cp_commit() {
    asm volatile("cp.async.commit_group;" ::: "memory");
}
__device__ __forceinline__ void cp_wait1() {
    asm volatile("cp.async.wait_group 1;" ::: "memory");
}
__device__ __forceinline__ void cp_wait0() {
    asm volatile("cp.async.wait_group 0;" ::: "memory");
}

// issue one stage of loads: A (128 x BK) hi/lo + B (128 x BK) hi/lo
__device__ __forceinline__ void issue_stage(
    uint32_t sbase,  // smem byte addr of stage
    const __nv_bfloat16* gAh, const __nv_bfloat16* gAl, size_t strideA,
    const __nv_bfloat16* gBh, const __nv_bfloat16* gBl, size_t strideB,
    int k0, int tid)
{
    const int r = tid >> 2;          // 0..63
    const int q = tid & 3;           // 16B chunk
    const uint32_t so = (uint32_t)((r * LDA + q * 8) * 2);
    const uint32_t so2 = (uint32_t)(((r + 64) * LDA + q * 8) * 2);
    const size_t go = (size_t)r * strideA + k0 + q * 8;
    const size_t go2 = (size_t)(r + 64) * strideA + k0 + q * 8;
    const size_t gb = (size_t)r * strideB + k0 + q * 8;
    const size_t gb2 = (size_t)(r + 64) * strideB + k0 + q * 8;

    cp_async16(sbase + so, gAh + go);
    cp_async16(sbase + so2, gAh + go2);
    cp_async16(sbase + TILE_E * 2 + so, gAl + go);
    cp_async16(sbase + TILE_E * 2 + so2, gAl + go2);
    cp_async16(sbase + 2 * TILE_E * 2 + so, gBh + gb);
    cp_async16(sbase + 2 * TILE_E * 2 + so2, gBh + gb2);
    cp_async16(sbase + 3 * TILE_E * 2 + so, gBl + gb);
    cp_async16(sbase + 3 * TILE_E * 2 + so2, gBl + gb2);
}

// ---------------------------------------------------------------------------
// TN mainloop with cp.async double buffering.
// acc[mt][nt][4] += A[i][k]*B[j][k], 3x bf16 split (AhBh + AhBl + AlBh).
// ---------------------------------------------------------------------------
__device__ __forceinline__ void mma_mainloop(
    const __nv_bfloat16* __restrict__ gAh, const __nv_bfloat16* __restrict__ gAl,
    size_t strideA,
    const __nv_bfloat16* __restrict__ gBh, const __nv_bfloat16* __restrict__ gBl,
    size_t strideB,
    int KTOT, char* smem, float acc[2][8][4])
{
    const int tid = threadIdx.x;
    const int lane = tid & 31, wid = tid >> 5;
    const int wm = (wid & 3) * 32;      // warp m origin
    const int wn = (wid >> 2) * 64;     // warp n origin

    const uint32_t sb = smem_u32(smem);

    // ldmatrix lane coordinates
    const int a_row = lane & 15;
    const int a_col = (lane >> 4) * 8;
    const int b_row = (lane & 7) + (lane >> 4) * 8;
    const int b_col = ((lane >> 3) & 1) * 8;

    const int iters = KTOT / BK;

    issue_stage(sb, gAh, gAl, strideA, gBh, gBl, strideB, 0, tid);
    cp_commit();

    for (int it = 0; it < iters; it++) {
        if (it + 1 < iters) {
            issue_stage(sb + ((it + 1) & 1) * STAGE_E * 2,
                        gAh, gAl, strideA, gBh, gBl, strideB, (it + 1) * BK, tid);
            cp_commit();
            cp_wait1();
        } else {
            cp_wait0();
        }
        __syncthreads();

        const uint32_t st = sb + (it & 1) * STAGE_E * 2;
#pragma unroll
        for (int kk = 0; kk < BK; kk += 16) {
            uint32_t ah[2][4], al[2][4];
#pragma unroll
            for (int mt = 0; mt < 2; mt++) {
                uint32_t ra = st + (uint32_t)(((wm + mt * 16 + a_row) * LDA + kk + a_col) * 2);
                ldsm_x4(ah[mt], ra);
                ldsm_x4(al[mt], ra + TILE_E * 2);
            }
#pragma unroll
            for (int g = 0; g < 4; g++) {
                uint32_t bh[4], bl[4];
                uint32_t rb = st + 2 * TILE_E * 2 +
                              (uint32_t)(((wn + g * 16 + b_row) * LDA + kk + b_col) * 2);
                ldsm_x4(bh, rb);
                ldsm_x4(bl, rb + TILE_E * 2);
#pragma unroll
                for (int half = 0; half < 2; half++) {
                    const int u = half * 2;
                    const int nt = g * 2 + half;
#pragma unroll
                    for (int mt = 0; mt < 2; mt++) {
                        mma_bf16(acc[mt][nt], ah[mt], &bh[u]);
                        mma_bf16(acc[mt][nt], ah[mt], &bl[u]);
                        mma_bf16(acc[mt][nt], al[mt], &bh[u]);
                    }
                }
            }
        }
        __syncthreads();
    }
}

// ---------------------------------------------------------------------------
// S = Q^T K : grid (8 jTiles, 8 iTiles, 32 z), 256 threads
// ---------------------------------------------------------------------------
__global__ void __launch_bounds__(256) attn_s_kernel(
    const __nv_bfloat16* __restrict__ Qh, const __nv_bfloat16* __restrict__ Ql,
    const __nv_bfloat16* __restrict__ Kh, const __nv_bfloat16* __restrict__ Kl,
    float* __restrict__ S)
{
    extern __shared__ char smem[];
    const int z = blockIdx.z;
    const int i0 = blockIdx.y * BM, j0 = blockIdx.x * BN;

    float acc[2][8][4] = {};
    mma_mainloop(Qh + ((size_t)z * NN_ + i0) * DD, Ql + ((size_t)z * NN_ + i0) * DD, DD,
                 Kh + ((size_t)z * NN_ + j0) * DD, Kl + ((size_t)z * NN_ + j0) * DD, DD,
                 DD, smem, acc);

    const int lane = threadIdx.x & 31, wid = threadIdx.x >> 5;
    const int wm = (wid & 3) * 32, wn = (wid >> 2) * 64;
#pragma unroll
    for (int mt = 0; mt < 2; mt++)
#pragma unroll
        for (int nt = 0; nt < 8; nt++) {
            int i = i0 + wm + mt * 16 + (lane >> 2);
            int j = j0 + wn + nt * 8 + 2 * (lane & 3);
            float* p0 = &S[((size_t)z * NN_ + i) * NN_ + j];
            float* p1 = &S[((size_t)z * NN_ + i + 8) * NN_ + j];
            *reinterpret_cast<float2*>(p0) = make_float2(acc[mt][nt][0], acc[mt][nt][1]);
            *reinterpret_cast<float2*>(p1) = make_float2(acc[mt][nt][2], acc[mt][nt][3]);
        }
}

// ---------------------------------------------------------------------------
// O = P V^T + epilogue : grid (2 dTiles, 8 iTiles, 32 z), 256 threads
// ---------------------------------------------------------------------------
__global__ void __launch_bounds__(256) attn_o_kernel(
    const __nv_bfloat16* __restrict__ Ph, const __nv_bfloat16* __restrict__ Pl,
    const __nv_bfloat16* __restrict__ Vh, const __nv_bfloat16* __restrict__ Vl,
    const float* __restrict__ YP, const float* __restrict__ gamma,
    float* __restrict__ out)
{
    extern __shared__ char smem[];
    const int z = blockIdx.z, b = z >> 3, h = z & 7;
    const int i0 = blockIdx.y * BM, d0 = blockIdx.x * BN;

    float acc[2][8][4] = {};
    mma_mainloop(Ph + ((size_t)z * NN_ + i0) * NN_, Pl + ((size_t)z * NN_ + i0) * NN_, NN_,
                 Vh + ((size_t)b * HD + h * DD + d0) * NN_,
                 Vl + ((size_t)b * HD + h * DD + d0) * NN_, NN_,
                 NN_, smem, acc);

    const int lane = threadIdx.x & 31, wid = threadIdx.x >> 5;
    const int wm = (wid & 3) * 32, wn = (wid >> 2) * 64;
    const float g = gamma[h];
    const float inv1pg = 1.0f / (1.0f + g);

#pragma unroll
    for (int mt = 0; mt < 2; mt++)
#pragma unroll
        for (int nt = 0; nt < 8; nt++) {
            int i = i0 + wm + mt * 16 + (lane >> 2);
            int d = d0 + wn + nt * 8 + 2 * (lane & 3);
#pragma unroll
            for (int u = 0; u < 4; u++) {
                int dd = d + (u & 1);
                int ii = i + (u >> 1) * 8;
                float yp = YP[((size_t)b * CC + dd) * NN_ + ii];
                out[((size_t)b * HD + h * DD + dd) * NN_ + ii] =
                    (g * acc[mt][nt][u] + yp) * inv1pg;
            }
        }
}

// ---------------------------------------------------------------------------
// SIMT NN GEMM for projections
// ---------------------------------------------------------------------------
__global__ void __launch_bounds__(256) gemm_nn_kernel(
    const float* __restrict__ A, const float* __restrict__ Bm,
    const float* __restrict__ bias, float* __restrict__ Cm,
    int M, int Nd, int Kd, size_t strideB, size_t strideC)
{
    __shared__ float As[16][64];
    __shared__ float Bs[16][64];
    const int z = blockIdx.z;
    const float* Bz = Bm + (size_t)z * strideB;
    float* Cz = Cm + (size_t)z * strideC;
    const int m0 = blockIdx.y * 64, n0 = blockIdx.x * 64;
    const int tid = threadIdx.x, tx = tid & 15, ty = tid >> 4;
    const int la_m = tid >> 2, la_k = (tid & 3) * 4;
    const int lb_k = tid >> 4, lb_n = (tid & 15) * 4;
    float acc[4][4] = {};
    for (int k0 = 0; k0 < Kd; k0 += 16) {
        float4 a4 = *reinterpret_cast<const float4*>(&A[(size_t)(m0 + la_m) * Kd + k0 + la_k]);
        As[la_k + 0][la_m] = a4.x; As[la_k + 1][la_m] = a4.y;
        As[la_k + 2][la_m] = a4.z; As[la_k + 3][la_m] = a4.w;
        *reinterpret_cast<float4*>(&Bs[lb_k][lb_n]) =
            *reinterpret_cast<const float4*>(&Bz[(size_t)(k0 + lb_k) * Nd + n0 + lb_n]);
        __syncthreads();
#pragma unroll
        for (int k = 0; k < 16; k++) {
            float a[4], bv[4];
#pragma unroll
            for (int i = 0; i < 4; i++) a[i] = As[k][ty * 4 + i];
#pragma unroll
            for (int j = 0; j < 4; j++) bv[j] = Bs[k][tx * 4 + j];
#pragma unroll
            for (int i = 0; i < 4; i++)
#pragma unroll
                for (int j = 0; j < 4; j++) acc[i][j] += a[i] * bv[j];
        }
        __syncthreads();
    }
#pragma unroll
    for (int i = 0; i < 4; i++) {
        int m = m0 + ty * 4 + i;
        float bv = bias ? bias[m] : 0.0f;
#pragma unroll
        for (int j = 0; j < 4; j++)
            Cz[(size_t)m * Nd + n0 + tx * 4 + j] = acc[i][j] + bv;
    }
}

// ---------------------------------------------------------------------------
// Transpose+split: [B][2048][1024] fp32 (b,h) slice -> [z][n][d] bf16 hi/lo
// ---------------------------------------------------------------------------
__global__ void __launch_bounds__(256) transpose_split_kernel(
    const float* __restrict__ in,
    __nv_bfloat16* __restrict__ oh, __nv_bfloat16* __restrict__ ol)
{
    __shared__ float t[32][33];
    const int z = blockIdx.z, b = z >> 3, h = z & 7;
    const int n0 = blockIdx.x * 32, d0 = blockIdx.y * 32;
    const int tx = threadIdx.x, ty = threadIdx.y;
    for (int r = ty; r < 32; r += 8)
        t[r][tx] = in[((size_t)b * HD + h * DD + d0 + r) * NN_ + n0 + tx];
    __syncthreads();
    for (int r = ty; r < 32; r += 8) {
        float v = t[tx][r];
        __nv_bfloat16 hi = __float2bfloat16(v);
        float lo = v - __bfloat162float(hi);
        size_t o = ((size_t)z * NN_ + n0 + r) * DD + d0 + tx;
        oh[o] = hi;
        ol[o] = __float2bfloat16(lo);
    }
}

__global__ void __launch_bounds__(256) split_kernel(
    const float* __restrict__ in,
    __nv_bfloat16* __restrict__ oh, __nv_bfloat16* __restrict__ ol, size_t n)
{
    size_t i = (size_t)blockIdx.x * blockDim.x + threadIdx.x;
    if (i < n) {
        float v = in[i];
        __nv_bfloat16 hi = __float2bfloat16(v);
        oh[i] = hi;
        ol[i] = __float2bfloat16(v - __bfloat162float(hi));
    }
}

// ---------------------------------------------------------------------------
// Row softmax over keys, emit bf16 hi/lo
// ---------------------------------------------------------------------------
__global__ void __launch_bounds__(256) softmax_kernel(
    const float* __restrict__ S,
    __nv_bfloat16* __restrict__ Ph, __nv_bfloat16* __restrict__ Pl)
{
    __shared__ float red[256];
    const size_t row = blockIdx.x;
    const float* r = S + row * NN_;
    const int tid = threadIdx.x;

    float v[4];
    float mx = -INFINITY;
#pragma unroll
    for (int j = 0; j < 4; j++) { v[j] = r[tid + j * 256]; mx = fmaxf(mx, v[j]); }
    red[tid] = mx;
    __syncthreads();
    for (int s = 128; s > 0; s >>= 1) {
        if (tid < s) red[tid] = fmaxf(red[tid], red[tid + s]);
        __syncthreads();
    }
    mx = red[0];
    __syncthreads();

    float sum = 0.0f;
#pragma unroll
    for (int j = 0; j < 4; j++) { v[j] = __expf(v[j] - mx); sum += v[j]; }
    red[tid] = sum;
    __syncthreads();
    for (int s = 128; s > 0; s >>= 1) {
        if (tid < s) red[tid] += red[tid + s];
        __syncthreads();
    }
    float inv = 1.0f / red[0];

#pragma unroll
    for (int j = 0; j < 4; j++) {
        float p = v[j] * inv;
        __nv_bfloat16 hi = __float2bfloat16(p);
        size_t o = row * NN_ + tid + j * 256;
        Ph[o] = hi;
        Pl[o] = __float2bfloat16(p - __bfloat162float(hi));
    }
}

// ---------------------------------------------------------------------------
extern "C" void kernel_launch(void* const* d_in, const int* in_sizes, int n_in,
                              void* d_out, int out_size)
{
    const float* x     = (const float*)d_in[0];
    const float* y     = (const float*)d_in[1];
    const float* Wq    = (const float*)d_in[2];
    const float* bq    = (const float*)d_in[3];
    const float* Wk    = (const float*)d_in[4];
    const float* bk    = (const float*)d_in[5];
    const float* Wv    = (const float*)d_in[6];
    const float* bv    = (const float*)d_in[7];
    const float* Wp    = (const float*)d_in[8];
    const float* gamma = (const float*)d_in[9];
    float* out = (float*)d_out;

    float *Q, *K, *V, *YP, *S;
    __nv_bfloat16 *Qth, *Qtl, *Kth, *Ktl, *Vh, *Vl, *Ph, *Pl;
    cudaGetSymbolAddress((void**)&Q,   g_Q);
    cudaGetSymbolAddress((void**)&K,   g_K);
    cudaGetSymbolAddress((void**)&V,   g_V);
    cudaGetSymbolAddress((void**)&YP,  g_YP);
    cudaGetSymbolAddress((void**)&S,   g_S);
    cudaGetSymbolAddress((void**)&Qth, g_Qth);
    cudaGetSymbolAddress((void**)&Qtl, g_Qtl);
    cudaGetSymbolAddress((void**)&Kth, g_Kth);
    cudaGetSymbolAddress((void**)&Ktl, g_Ktl);
    cudaGetSymbolAddress((void**)&Vh,  g_Vh);
    cudaGetSymbolAddress((void**)&Vl,  g_Vl);
    cudaGetSymbolAddress((void**)&Ph,  g_Ph);
    cudaGetSymbolAddress((void**)&Pl,  g_Pl);

    cudaFuncSetAttribute(attn_s_kernel, cudaFuncAttributeMaxDynamicSharedMemorySize, SMEM_BYTES);
    cudaFuncSetAttribute(attn_o_kernel, cudaFuncAttributeMaxDynamicSharedMemorySize, SMEM_BYTES);

    dim3 t(256);

    // Projections (SIMT fp32)
    gemm_nn_kernel<<<dim3(16, 32, BB), t>>>(Wq, x, bq, Q, HD, NN_, CC,
                                            (size_t)CC * NN_, (size_t)HD * NN_);
    gemm_nn_kernel<<<dim3(16, 32, BB), t>>>(Wk, x, bk, K, HD, NN_, CC,
                                            (size_t)CC * NN_, (size_t)HD * NN_);
    gemm_nn_kernel<<<dim3(16, 32, BB), t>>>(Wv, y, bv, V, HD, NN_, CC,
                                            (size_t)CC * NN_, (size_t)HD * NN_);
    gemm_nn_kernel<<<dim3(16, 4, BB), t>>>(Wp, y, nullptr, YP, CC, NN_, CC,
                                           (size_t)CC * NN_, (size_t)CC * NN_);

    // Split / transpose into bf16 hi/lo
    transpose_split_kernel<<<dim3(32, 8, ZZ), dim3(32, 8)>>>(Q, Qth, Qtl);
    transpose_split_kernel<<<dim3(32, 8, ZZ), dim3(32, 8)>>>(K, Kth, Ktl);
    {
        size_t n = (size_t)BB * HD * NN_;
        split_kernel<<<(unsigned)((n + 255) / 256), t>>>(V, Vh, Vl, n);
    }

    // S = Q^T K (mma.sync bf16 3x-split, cp.async pipelined)
    attn_s_kernel<<<dim3(8, 8, ZZ), t, SMEM_BYTES>>>(Qth, Qtl, Kth, Ktl, S);

    // softmax -> P hi/lo
    softmax_kernel<<<ZZ * NN_, t>>>(S, Ph, Pl);

    // O = P V^T + epilogue (mma.sync bf16 3x-split, cp.async pipelined)
    attn_o_kernel<<<dim3(2, 8, ZZ), t, SMEM_BYTES>>>(Ph, Pl, Vh, Vl, YP, gamma, out);
}

// round 6
// speedup vs baseline: 2.3312x; 1.4423x over previous
#include <cuda_runtime.h>
#include <cuda_bf16.h>
#include <math.h>
#include <stdint.h>

// Problem constants
#define BB 4
#define CC 256
#define NN_ 1024
#define HH 8
#define DD 256
#define HD 2048
#define ZZ 32   // B*H

// Attention / projection GEMM tiling
#define BM 128
#define BN 128
#define BK 32
#define LDA 40                 // padded row length (bf16 elems) = 80 B
#define TILE_E (128 * LDA)     // elems per operand tile
#define STAGE_E (4 * TILE_E)   // Ah, Al, Bh, Bl
#define SMEM_BYTES (2 * STAGE_E * 2)   // 2 stages * bytes

// ---------------- scratch (__device__ globals: allocation-free) -------------
__device__ __align__(256) float g_Q[(size_t)BB * HD * NN_];
__device__ __align__(256) float g_K[(size_t)BB * HD * NN_];
__device__ __align__(256) float g_YP[(size_t)BB * CC * NN_];
__device__ __align__(256) float g_S[(size_t)ZZ * NN_ * NN_];

// weights split
__device__ __align__(256) __nv_bfloat16 g_Wqh[(size_t)HD * CC];
__device__ __align__(256) __nv_bfloat16 g_Wql[(size_t)HD * CC];
__device__ __align__(256) __nv_bfloat16 g_Wkh[(size_t)HD * CC];
__device__ __align__(256) __nv_bfloat16 g_Wkl[(size_t)HD * CC];
__device__ __align__(256) __nv_bfloat16 g_Wvh[(size_t)HD * CC];
__device__ __align__(256) __nv_bfloat16 g_Wvl[(size_t)HD * CC];
__device__ __align__(256) __nv_bfloat16 g_Wph[(size_t)CC * CC];
__device__ __align__(256) __nv_bfloat16 g_Wpl[(size_t)CC * CC];

// inputs transposed+split: [B][N][C]
__device__ __align__(256) __nv_bfloat16 g_Xth[(size_t)BB * NN_ * CC];
__device__ __align__(256) __nv_bfloat16 g_Xtl[(size_t)BB * NN_ * CC];
__device__ __align__(256) __nv_bfloat16 g_Yth[(size_t)BB * NN_ * CC];
__device__ __align__(256) __nv_bfloat16 g_Ytl[(size_t)BB * NN_ * CC];

// attention operands
__device__ __align__(256) __nv_bfloat16 g_Qth[(size_t)ZZ * NN_ * DD];
__device__ __align__(256) __nv_bfloat16 g_Qtl[(size_t)ZZ * NN_ * DD];
__device__ __align__(256) __nv_bfloat16 g_Kth[(size_t)ZZ * NN_ * DD];
__device__ __align__(256) __nv_bfloat16 g_Ktl[(size_t)ZZ * NN_ * DD];
__device__ __align__(256) __nv_bfloat16 g_Vh[(size_t)BB * HD * NN_];
__device__ __align__(256) __nv_bfloat16 g_Vl[(size_t)BB * HD * NN_];
__device__ __align__(256) __nv_bfloat16 g_Ph[(size_t)ZZ * NN_ * NN_];
__device__ __align__(256) __nv_bfloat16 g_Pl[(size_t)ZZ * NN_ * NN_];

// ---------------- helpers ---------------------------------------------------
__device__ __forceinline__ uint32_t smem_u32(const void* p) {
    uint32_t a;
    asm("{ .reg .u64 t; cvta.to.shared.u64 t, %1; cvt.u32.u64 %0, t; }"
        : "=r"(a) : "l"(p));
    return a;
}
__device__ __forceinline__ void ldsm_x4(uint32_t* r, uint32_t addr) {
    asm volatile("ldmatrix.sync.aligned.m8n8.x4.shared.b16 {%0,%1,%2,%3}, [%4];"
                 : "=r"(r[0]), "=r"(r[1]), "=r"(r[2]), "=r"(r[3]) : "r"(addr));
}
__device__ __forceinline__ void mma_bf16(float* c, const uint32_t* a, const uint32_t* b) {
    asm volatile(
        "mma.sync.aligned.m16n8k16.row.col.f32.bf16.bf16.f32 "
        "{%0,%1,%2,%3}, {%4,%5,%6,%7}, {%8,%9}, {%0,%1,%2,%3};"
        : "+f"(c[0]), "+f"(c[1]), "+f"(c[2]), "+f"(c[3])
        : "r"(a[0]), "r"(a[1]), "r"(a[2]), "r"(a[3]), "r"(b[0]), "r"(b[1]));
}
__device__ __forceinline__ void cp_async16(uint32_t sm, const void* g) {
    asm volatile("cp.async.cg.shared.global [%0], [%1], 16;" :: "r"(sm), "l"(g));
}
__device__ __forceinline__ void cp_commit() {
    asm volatile("cp.async.commit_group;" ::: "memory");
}
__device__ __forceinline__ void cp_wait1() {
    asm volatile("cp.async.wait_group 1;" ::: "memory");
}
__device__ __forceinline__ void cp_wait0() {
    asm volatile("cp.async.wait_group 0;" ::: "memory");
}

// issue one stage of loads: A (128 x BK) hi/lo + B (128 x BK) hi/lo
__device__ __forceinline__ void issue_stage(
    uint32_t sbase,
    const __nv_bfloat16* gAh, const __nv_bfloat16* gAl, size_t strideA,
    const __nv_bfloat16* gBh, const __nv_bfloat16* gBl, size_t strideB,
    int k0, int tid)
{
    const int r = tid >> 2;
    const int q = tid & 3;
    const uint32_t so = (uint32_t)((r * LDA + q * 8) * 2);
    const uint32_t so2 = (uint32_t)(((r + 64) * LDA + q * 8) * 2);
    const size_t go = (size_t)r * strideA + k0 + q * 8;
    const size_t go2 = (size_t)(r + 64) * strideA + k0 + q * 8;
    const size_t gb = (size_t)r * strideB + k0 + q * 8;
    const size_t gb2 = (size_t)(r + 64) * strideB + k0 + q * 8;

    cp_async16(sbase + so, gAh + go);
    cp_async16(sbase + so2, gAh + go2);
    cp_async16(sbase + TILE_E * 2 + so, gAl + go);
    cp_async16(sbase + TILE_E * 2 + so2, gAl + go2);
    cp_async16(sbase + 2 * TILE_E * 2 + so, gBh + gb);
    cp_async16(sbase + 2 * TILE_E * 2 + so2, gBh + gb2);
    cp_async16(sbase + 3 * TILE_E * 2 + so, gBl + gb);
    cp_async16(sbase + 3 * TILE_E * 2 + so2, gBl + gb2);
}

// ---------------------------------------------------------------------------
// TN mainloop with cp.async double buffering.
// acc[mt][nt][4] += A[i][k]*B[j][k], 3x bf16 split (AhBh + AhBl + AlBh).
// ---------------------------------------------------------------------------
__device__ __forceinline__ void mma_mainloop(
    const __nv_bfloat16* __restrict__ gAh, const __nv_bfloat16* __restrict__ gAl,
    size_t strideA,
    const __nv_bfloat16* __restrict__ gBh, const __nv_bfloat16* __restrict__ gBl,
    size_t strideB,
    int KTOT, char* smem, float acc[2][8][4])
{
    const int tid = threadIdx.x;
    const int lane = tid & 31, wid = tid >> 5;
    const int wm = (wid & 3) * 32;
    const int wn = (wid >> 2) * 64;

    const uint32_t sb = smem_u32(smem);

    const int a_row = lane & 15;
    const int a_col = (lane >> 4) * 8;
    const int b_row = (lane & 7) + (lane >> 4) * 8;
    const int b_col = ((lane >> 3) & 1) * 8;

    const int iters = KTOT / BK;

    issue_stage(sb, gAh, gAl, strideA, gBh, gBl, strideB, 0, tid);
    cp_commit();

    for (int it = 0; it < iters; it++) {
        if (it + 1 < iters) {
            issue_stage(sb + ((it + 1) & 1) * STAGE_E * 2,
                        gAh, gAl, strideA, gBh, gBl, strideB, (it + 1) * BK, tid);
            cp_commit();
            cp_wait1();
        } else {
            cp_wait0();
        }
        __syncthreads();

        const uint32_t st = sb + (it & 1) * STAGE_E * 2;
#pragma unroll
        for (int kk = 0; kk < BK; kk += 16) {
            uint32_t ah[2][4], al[2][4];
#pragma unroll
            for (int mt = 0; mt < 2; mt++) {
                uint32_t ra = st + (uint32_t)(((wm + mt * 16 + a_row) * LDA + kk + a_col) * 2);
                ldsm_x4(ah[mt], ra);
                ldsm_x4(al[mt], ra + TILE_E * 2);
            }
#pragma unroll
            for (int g = 0; g < 4; g++) {
                uint32_t bh[4], bl[4];
                uint32_t rb = st + 2 * TILE_E * 2 +
                              (uint32_t)(((wn + g * 16 + b_row) * LDA + kk + b_col) * 2);
                ldsm_x4(bh, rb);
                ldsm_x4(bl, rb + TILE_E * 2);
#pragma unroll
                for (int half = 0; half < 2; half++) {
                    const int u = half * 2;
                    const int nt = g * 2 + half;
#pragma unroll
                    for (int mt = 0; mt < 2; mt++) {
                        mma_bf16(acc[mt][nt], ah[mt], &bh[u]);
                        mma_bf16(acc[mt][nt], ah[mt], &bl[u]);
                        mma_bf16(acc[mt][nt], al[mt], &bh[u]);
                    }
                }
            }
        }
        __syncthreads();
    }
}

// ---------------------------------------------------------------------------
// Projection GEMM (HMMA): out[z][m][n] = sum_c W[m][c] * Xt[z][n][c] (+ bias)
// mode: outF != null -> fp32 [B][M][1024]; else bf16 hi/lo split outputs.
// grid (N/128, M/128, B), 256 threads
// ---------------------------------------------------------------------------
__global__ void __launch_bounds__(256) proj_mma_kernel(
    const __nv_bfloat16* __restrict__ Wh, const __nv_bfloat16* __restrict__ Wl,
    const __nv_bfloat16* __restrict__ Xh, const __nv_bfloat16* __restrict__ Xl,
    const float* __restrict__ bias,
    float* __restrict__ outF,
    __nv_bfloat16* __restrict__ outH, __nv_bfloat16* __restrict__ outL,
    int M)
{
    extern __shared__ char smem[];
    const int z = blockIdx.z;
    const int m0 = blockIdx.y * BM, n0 = blockIdx.x * BN;

    float acc[2][8][4] = {};
    mma_mainloop(Wh + (size_t)m0 * CC, Wl + (size_t)m0 * CC, CC,
                 Xh + ((size_t)z * NN_ + n0) * CC, Xl + ((size_t)z * NN_ + n0) * CC, CC,
                 CC, smem, acc);

    const int lane = threadIdx.x & 31, wid = threadIdx.x >> 5;
    const int wm = (wid & 3) * 32, wn = (wid >> 2) * 64;
#pragma unroll
    for (int mt = 0; mt < 2; mt++)
#pragma unroll
        for (int nt = 0; nt < 8; nt++) {
            int m = m0 + wm + mt * 16 + (lane >> 2);
            int n = n0 + wn + nt * 8 + 2 * (lane & 3);
            float b0 = bias ? bias[m] : 0.0f;
            float b1 = bias ? bias[m + 8] : 0.0f;
            float v00 = acc[mt][nt][0] + b0, v01 = acc[mt][nt][1] + b0;
            float v10 = acc[mt][nt][2] + b1, v11 = acc[mt][nt][3] + b1;
            if (outF) {
                *reinterpret_cast<float2*>(&outF[((size_t)z * M + m) * NN_ + n]) =
                    make_float2(v00, v01);
                *reinterpret_cast<float2*>(&outF[((size_t)z * M + m + 8) * NN_ + n]) =
                    make_float2(v10, v11);
            } else {
                __nv_bfloat16 h00 = __float2bfloat16(v00), h01 = __float2bfloat16(v01);
                __nv_bfloat16 h10 = __float2bfloat16(v10), h11 = __float2bfloat16(v11);
                __nv_bfloat162 hp0; hp0.x = h00; hp0.y = h01;
                __nv_bfloat162 hp1; hp1.x = h10; hp1.y = h11;
                __nv_bfloat162 lp0;
                lp0.x = __float2bfloat16(v00 - __bfloat162float(h00));
                lp0.y = __float2bfloat16(v01 - __bfloat162float(h01));
                __nv_bfloat162 lp1;
                lp1.x = __float2bfloat16(v10 - __bfloat162float(h10));
                lp1.y = __float2bfloat16(v11 - __bfloat162float(h11));
                *reinterpret_cast<__nv_bfloat162*>(&outH[((size_t)z * M + m) * NN_ + n]) = hp0;
                *reinterpret_cast<__nv_bfloat162*>(&outH[((size_t)z * M + m + 8) * NN_ + n]) = hp1;
                *reinterpret_cast<__nv_bfloat162*>(&outL[((size_t)z * M + m) * NN_ + n]) = lp0;
                *reinterpret_cast<__nv_bfloat162*>(&outL[((size_t)z * M + m + 8) * NN_ + n]) = lp1;
            }
        }
}

// ---------------------------------------------------------------------------
// S = Q^T K : grid (8 jTiles, 8 iTiles, 32 z), 256 threads
// ---------------------------------------------------------------------------
__global__ void __launch_bounds__(256) attn_s_kernel(
    const __nv_bfloat16* __restrict__ Qh, const __nv_bfloat16* __restrict__ Ql,
    const __nv_bfloat16* __restrict__ Kh, const __nv_bfloat16* __restrict__ Kl,
    float* __restrict__ S)
{
    extern __shared__ char smem[];
    const int z = blockIdx.z;
    const int i0 = blockIdx.y * BM, j0 = blockIdx.x * BN;

    float acc[2][8][4] = {};
    mma_mainloop(Qh + ((size_t)z * NN_ + i0) * DD, Ql + ((size_t)z * NN_ + i0) * DD, DD,
                 Kh + ((size_t)z * NN_ + j0) * DD, Kl + ((size_t)z * NN_ + j0) * DD, DD,
                 DD, smem, acc);

    const int lane = threadIdx.x & 31, wid = threadIdx.x >> 5;
    const int wm = (wid & 3) * 32, wn = (wid >> 2) * 64;
#pragma unroll
    for (int mt = 0; mt < 2; mt++)
#pragma unroll
        for (int nt = 0; nt < 8; nt++) {
            int i = i0 + wm + mt * 16 + (lane >> 2);
            int j = j0 + wn + nt * 8 + 2 * (lane & 3);
            float* p0 = &S[((size_t)z * NN_ + i) * NN_ + j];
            float* p1 = &S[((size_t)z * NN_ + i + 8) * NN_ + j];
            *reinterpret_cast<float2*>(p0) = make_float2(acc[mt][nt][0], acc[mt][nt][1]);
            *reinterpret_cast<float2*>(p1) = make_float2(acc[mt][nt][2], acc[mt][nt][3]);
        }
}

// ---------------------------------------------------------------------------
// O = P V^T + epilogue : grid (2 dTiles, 8 iTiles, 32 z), 256 threads
// ---------------------------------------------------------------------------
__global__ void __launch_bounds__(256) attn_o_kernel(
    const __nv_bfloat16* __restrict__ Ph, const __nv_bfloat16* __restrict__ Pl,
    const __nv_bfloat16* __restrict__ Vh, const __nv_bfloat16* __restrict__ Vl,
    const float* __restrict__ YP, const float* __restrict__ gamma,
    float* __restrict__ out)
{
    extern __shared__ char smem[];
    const int z = blockIdx.z, b = z >> 3, h = z & 7;
    const int i0 = blockIdx.y * BM, d0 = blockIdx.x * BN;

    float acc[2][8][4] = {};
    mma_mainloop(Ph + ((size_t)z * NN_ + i0) * NN_, Pl + ((size_t)z * NN_ + i0) * NN_, NN_,
                 Vh + ((size_t)b * HD + h * DD + d0) * NN_,
                 Vl + ((size_t)b * HD + h * DD + d0) * NN_, NN_,
                 NN_, smem, acc);

    const int lane = threadIdx.x & 31, wid = threadIdx.x >> 5;
    const int wm = (wid & 3) * 32, wn = (wid >> 2) * 64;
    const float g = gamma[h];
    const float inv1pg = 1.0f / (1.0f + g);

#pragma unroll
    for (int mt = 0; mt < 2; mt++)
#pragma unroll
        for (int nt = 0; nt < 8; nt++) {
            int i = i0 + wm + mt * 16 + (lane >> 2);
            int d = d0 + wn + nt * 8 + 2 * (lane & 3);
#pragma unroll
            for (int u = 0; u < 4; u++) {
                int dd = d + (u & 1);
                int ii = i + (u >> 1) * 8;
                float yp = YP[((size_t)b * CC + dd) * NN_ + ii];
                out[((size_t)b * HD + h * DD + dd) * NN_ + ii] =
                    (g * acc[mt][nt][u] + yp) * inv1pg;
            }
        }
}

// ---------------------------------------------------------------------------
// Transpose+split input: [B][C=256][N] fp32 -> [B][N][C] bf16 hi/lo
// grid (N/32, C/32, B), block (32, 8)
// ---------------------------------------------------------------------------
__global__ void __launch_bounds__(256) transpose_split_in_kernel(
    const float* __restrict__ in,
    __nv_bfloat16* __restrict__ oh, __nv_bfloat16* __restrict__ ol)
{
    __shared__ float t[32][33];
    const int bz = blockIdx.z;
    const int n0 = blockIdx.x * 32, c0 = blockIdx.y * 32;
    const int tx = threadIdx.x, ty = threadIdx.y;
    for (int r = ty; r < 32; r += 8)
        t[r][tx] = in[((size_t)bz * CC + c0 + r) * NN_ + n0 + tx];
    __syncthreads();
    for (int r = ty; r < 32; r += 8) {
        float v = t[tx][r];
        __nv_bfloat16 hi = __float2bfloat16(v);
        size_t o = ((size_t)bz * NN_ + n0 + r) * CC + c0 + tx;
        oh[o] = hi;
        ol[o] = __float2bfloat16(v - __bfloat162float(hi));
    }
}

// ---------------------------------------------------------------------------
// Transpose+split Q/K: [B][2048][1024] fp32 (b,h) slice -> [z][n][d] bf16 hi/lo
// ---------------------------------------------------------------------------
__global__ void __launch_bounds__(256) transpose_split_kernel(
    const float* __restrict__ in,
    __nv_bfloat16* __restrict__ oh, __nv_bfloat16* __restrict__ ol)
{
    __shared__ float t[32][33];
    const int z = blockIdx.z, b = z >> 3, h = z & 7;
    const int n0 = blockIdx.x * 32, d0 = blockIdx.y * 32;
    const int tx = threadIdx.x, ty = threadIdx.y;
    for (int r = ty; r < 32; r += 8)
        t[r][tx] = in[((size_t)b * HD + h * DD + d0 + r) * NN_ + n0 + tx];
    __syncthreads();
    for (int r = ty; r < 32; r += 8) {
        float v = t[tx][r];
        __nv_bfloat16 hi = __float2bfloat16(v);
        size_t o = ((size_t)z * NN_ + n0 + r) * DD + d0 + tx;
        oh[o] = hi;
        ol[o] = __float2bfloat16(v - __bfloat162float(hi));
    }
}

// generic elementwise split (used for weights)
__global__ void __launch_bounds__(256) split_kernel(
    const float* __restrict__ in,
    __nv_bfloat16* __restrict__ oh, __nv_bfloat16* __restrict__ ol, int n)
{
    int i = blockIdx.x * blockDim.x + threadIdx.x;
    if (i < n) {
        float v = in[i];
        __nv_bfloat16 hi = __float2bfloat16(v);
        oh[i] = hi;
        ol[i] = __float2bfloat16(v - __bfloat162float(hi));
    }
}

// ---------------------------------------------------------------------------
// Row softmax over keys, emit bf16 hi/lo
// ---------------------------------------------------------------------------
__global__ void __launch_bounds__(256) softmax_kernel(
    const float* __restrict__ S,
    __nv_bfloat16* __restrict__ Ph, __nv_bfloat16* __restrict__ Pl)
{
    __shared__ float red[256];
    const size_t row = blockIdx.x;
    const float* r = S + row * NN_;
    const int tid = threadIdx.x;

    float v[4];
    float mx = -INFINITY;
#pragma unroll
    for (int j = 0; j < 4; j++) { v[j] = r[tid + j * 256]; mx = fmaxf(mx, v[j]); }
    red[tid] = mx;
    __syncthreads();
    for (int s = 128; s > 0; s >>= 1) {
        if (tid < s) red[tid] = fmaxf(red[tid], red[tid + s]);
        __syncthreads();
    }
    mx = red[0];
    __syncthreads();

    float sum = 0.0f;
#pragma unroll
    for (int j = 0; j < 4; j++) { v[j] = __expf(v[j] - mx); sum += v[j]; }
    red[tid] = sum;
    __syncthreads();
    for (int s = 128; s > 0; s >>= 1) {
        if (tid < s) red[tid] += red[tid + s];
        __syncthreads();
    }
    float inv = 1.0f / red[0];

#pragma unroll
    for (int j = 0; j < 4; j++) {
        float p = v[j] * inv;
        __nv_bfloat16 hi = __float2bfloat16(p);
        size_t o = row * NN_ + tid + j * 256;
        Ph[o] = hi;
        Pl[o] = __float2bfloat16(p - __bfloat162float(hi));
    }
}

// ---------------------------------------------------------------------------
extern "C" void kernel_launch(void* const* d_in, const int* in_sizes, int n_in,
                              void* d_out, int out_size)
{
    const float* x     = (const float*)d_in[0];
    const float* y     = (const float*)d_in[1];
    const float* Wq    = (const float*)d_in[2];
    const float* bq    = (const float*)d_in[3];
    const float* Wk    = (const float*)d_in[4];
    const float* bk    = (const float*)d_in[5];
    const float* Wv    = (const float*)d_in[6];
    const float* bv    = (const float*)d_in[7];
    const float* Wp    = (const float*)d_in[8];
    const float* gamma = (const float*)d_in[9];
    float* out = (float*)d_out;

    float *Q, *K, *YP, *S;
    __nv_bfloat16 *Wqh, *Wql, *Wkh, *Wkl, *Wvh, *Wvl, *Wph, *Wpl;
    __nv_bfloat16 *Xth, *Xtl, *Yth, *Ytl;
    __nv_bfloat16 *Qth, *Qtl, *Kth, *Ktl, *Vh, *Vl, *Ph, *Pl;
    cudaGetSymbolAddress((void**)&Q,   g_Q);
    cudaGetSymbolAddress((void**)&K,   g_K);
    cudaGetSymbolAddress((void**)&YP,  g_YP);
    cudaGetSymbolAddress((void**)&S,   g_S);
    cudaGetSymbolAddress((void**)&Wqh, g_Wqh);
    cudaGetSymbolAddress((void**)&Wql, g_Wql);
    cudaGetSymbolAddress((void**)&Wkh, g_Wkh);
    cudaGetSymbolAddress((void**)&Wkl, g_Wkl);
    cudaGetSymbolAddress((void**)&Wvh, g_Wvh);
    cudaGetSymbolAddress((void**)&Wvl, g_Wvl);
    cudaGetSymbolAddress((void**)&Wph, g_Wph);
    cudaGetSymbolAddress((void**)&Wpl, g_Wpl);
    cudaGetSymbolAddress((void**)&Xth, g_Xth);
    cudaGetSymbolAddress((void**)&Xtl, g_Xtl);
    cudaGetSymbolAddress((void**)&Yth, g_Yth);
    cudaGetSymbolAddress((void**)&Ytl, g_Ytl);
    cudaGetSymbolAddress((void**)&Qth, g_Qth);
    cudaGetSymbolAddress((void**)&Qtl, g_Qtl);
    cudaGetSymbolAddress((void**)&Kth, g_Kth);
    cudaGetSymbolAddress((void**)&Ktl, g_Ktl);
    cudaGetSymbolAddress((void**)&Vh,  g_Vh);
    cudaGetSymbolAddress((void**)&Vl,  g_Vl);
    cudaGetSymbolAddress((void**)&Ph,  g_Ph);
    cudaGetSymbolAddress((void**)&Pl,  g_Pl);

    cudaFuncSetAttribute(proj_mma_kernel, cudaFuncAttributeMaxDynamicSharedMemorySize, SMEM_BYTES);
    cudaFuncSetAttribute(attn_s_kernel, cudaFuncAttributeMaxDynamicSharedMemorySize, SMEM_BYTES);
    cudaFuncSetAttribute(attn_o_kernel, cudaFuncAttributeMaxDynamicSharedMemorySize, SMEM_BYTES);

    dim3 t(256);

    // Weight splits (bf16 hi/lo)
    split_kernel<<<(HD * CC + 255) / 256, t>>>(Wq, Wqh, Wql, HD * CC);
    split_kernel<<<(HD * CC + 255) / 256, t>>>(Wk, Wkh, Wkl, HD * CC);
    split_kernel<<<(HD * CC + 255) / 256, t>>>(Wv, Wvh, Wvl, HD * CC);
    split_kernel<<<(CC * CC + 255) / 256, t>>>(Wp, Wph, Wpl, CC * CC);

    // Input transposes+splits: [B][C][N] -> [B][N][C]
    transpose_split_in_kernel<<<dim3(32, 8, BB), dim3(32, 8)>>>(x, Xth, Xtl);
    transpose_split_in_kernel<<<dim3(32, 8, BB), dim3(32, 8)>>>(y, Yth, Ytl);

    // Projections (HMMA):
    proj_mma_kernel<<<dim3(8, 16, BB), t, SMEM_BYTES>>>(
        Wqh, Wql, Xth, Xtl, bq, Q, nullptr, nullptr, HD);
    proj_mma_kernel<<<dim3(8, 16, BB), t, SMEM_BYTES>>>(
        Wkh, Wkl, Xth, Xtl, bk, K, nullptr, nullptr, HD);
    proj_mma_kernel<<<dim3(8, 16, BB), t, SMEM_BYTES>>>(
        Wvh, Wvl, Yth, Ytl, bv, nullptr, Vh, Vl, HD);   // V split fused
    proj_mma_kernel<<<dim3(8, 2, BB), t, SMEM_BYTES>>>(
        Wph, Wpl, Yth, Ytl, nullptr, YP, nullptr, nullptr, CC);

    // Q/K transpose+split to [z][n][d]
    transpose_split_kernel<<<dim3(32, 8, ZZ), dim3(32, 8)>>>(Q, Qth, Qtl);
    transpose_split_kernel<<<dim3(32, 8, ZZ), dim3(32, 8)>>>(K, Kth, Ktl);

    // S = Q^T K (mma.sync bf16 3x-split, cp.async pipelined)
    attn_s_kernel<<<dim3(8, 8, ZZ), t, SMEM_BYTES>>>(Qth, Qtl, Kth, Ktl, S);

    // softmax -> P hi/lo
    softmax_kernel<<<ZZ * NN_, t>>>(S, Ph, Pl);

    // O = P V^T + epilogue (mma.sync bf16 3x-split, cp.async pipelined)
    attn_o_kernel<<<dim3(2, 8, ZZ), t, SMEM_BYTES>>>(Ph, Pl, Vh, Vl, YP, gamma, out);
}

// round 7
// speedup vs baseline: 2.5616x; 1.0988x over previous
#include <cuda_runtime.h>
#include <cuda_bf16.h>
#include <math.h>
#include <stdint.h>

// Problem constants
#define BB 4
#define CC 256
#define NN_ 1024
#define HH 8
#define DD 256
#define HD 2048
#define ZZ 32   // B*H

// j-major GEMM tiling (attn_o, proj)
#define BM 128
#define BN 128
#define BK 32
#define LDA 40                 // padded row length (bf16 elems) = 80 B
#define TILE_E (128 * LDA)
#define STAGE_E (4 * TILE_E)
#define SMEM_BYTES (2 * STAGE_E * 2)

// k-major tiling (attn_s: tiles are [BK=32 k-rows][128 cols])
#define LDB_KT 136             // padded cols (272 B rows) -> conflict-free trans ldsm
#define TILE_KT (32 * LDB_KT)
#define STAGE_KT (4 * TILE_KT)
#define SMEM_S_BYTES (2 * STAGE_KT * 2)

// ---------------- scratch (__device__ globals: allocation-free) -------------
__device__ __align__(256) float g_YP[(size_t)BB * CC * NN_];
__device__ __align__(256) float g_S[(size_t)ZZ * NN_ * NN_];

// weights split
__device__ __align__(256) __nv_bfloat16 g_Wqh[(size_t)HD * CC];
__device__ __align__(256) __nv_bfloat16 g_Wql[(size_t)HD * CC];
__device__ __align__(256) __nv_bfloat16 g_Wkh[(size_t)HD * CC];
__device__ __align__(256) __nv_bfloat16 g_Wkl[(size_t)HD * CC];
__device__ __align__(256) __nv_bfloat16 g_Wvh[(size_t)HD * CC];
__device__ __align__(256) __nv_bfloat16 g_Wvl[(size_t)HD * CC];
__device__ __align__(256) __nv_bfloat16 g_Wph[(size_t)CC * CC];
__device__ __align__(256) __nv_bfloat16 g_Wpl[(size_t)CC * CC];

// inputs transposed+split: [B][N][C]
__device__ __align__(256) __nv_bfloat16 g_Xth[(size_t)BB * NN_ * CC];
__device__ __align__(256) __nv_bfloat16 g_Xtl[(size_t)BB * NN_ * CC];
__device__ __align__(256) __nv_bfloat16 g_Yth[(size_t)BB * NN_ * CC];
__device__ __align__(256) __nv_bfloat16 g_Ytl[(size_t)BB * NN_ * CC];

// projection outputs, d-major [B][HD][N] bf16 hi/lo
__device__ __align__(256) __nv_bfloat16 g_Qh[(size_t)BB * HD * NN_];
__device__ __align__(256) __nv_bfloat16 g_Ql[(size_t)BB * HD * NN_];
__device__ __align__(256) __nv_bfloat16 g_Kh[(size_t)BB * HD * NN_];
__device__ __align__(256) __nv_bfloat16 g_Kl[(size_t)BB * HD * NN_];
__device__ __align__(256) __nv_bfloat16 g_Vh[(size_t)BB * HD * NN_];
__device__ __align__(256) __nv_bfloat16 g_Vl[(size_t)BB * HD * NN_];

// probabilities
__device__ __align__(256) __nv_bfloat16 g_Ph[(size_t)ZZ * NN_ * NN_];
__device__ __align__(256) __nv_bfloat16 g_Pl[(size_t)ZZ * NN_ * NN_];

// ---------------- helpers ---------------------------------------------------
__device__ __forceinline__ uint32_t smem_u32(const void* p) {
    uint32_t a;
    asm("{ .reg .u64 t; cvta.to.shared.u64 t, %1; cvt.u32.u64 %0, t; }"
        : "=r"(a) : "l"(p));
    return a;
}
__device__ __forceinline__ void ldsm_x4(uint32_t* r, uint32_t addr) {
    asm volatile("ldmatrix.sync.aligned.m8n8.x4.shared.b16 {%0,%1,%2,%3}, [%4];"
                 : "=r"(r[0]), "=r"(r[1]), "=r"(r[2]), "=r"(r[3]) : "r"(addr));
}
__device__ __forceinline__ void ldsm_x4_t(uint32_t* r, uint32_t addr) {
    asm volatile("ldmatrix.sync.aligned.m8n8.x4.trans.shared.b16 {%0,%1,%2,%3}, [%4];"
                 : "=r"(r[0]), "=r"(r[1]), "=r"(r[2]), "=r"(r[3]) : "r"(addr));
}
__device__ __forceinline__ void mma_bf16(float* c, const uint32_t* a, const uint32_t* b) {
    asm volatile(
        "mma.sync.aligned.m16n8k16.row.col.f32.bf16.bf16.f32 "
        "{%0,%1,%2,%3}, {%4,%5,%6,%7}, {%8,%9}, {%0,%1,%2,%3};"
        : "+f"(c[0]), "+f"(c[1]), "+f"(c[2]), "+f"(c[3])
        : "r"(a[0]), "r"(a[1]), "r"(a[2]), "r"(a[3]), "r"(b[0]), "r"(b[1]));
}
__device__ __forceinline__ void cp_async16(uint32_t sm, const void* g) {
    asm volatile("cp.async.cg.shared.global [%0], [%1], 16;" :: "r"(sm), "l"(g));
}
__device__ __forceinline__ void cp_commit() {
    asm volatile("cp.async.commit_group;" ::: "memory");
}
__device__ __forceinline__ void cp_wait1() {
    asm volatile("cp.async.wait_group 1;" ::: "memory");
}
__device__ __forceinline__ void cp_wait0() {
    asm volatile("cp.async.wait_group 0;" ::: "memory");
}

// ===========================================================================
// j-major mainloop (attn_o, proj): operands stored [row][k], non-trans ldsm
// ===========================================================================
__device__ __forceinline__ void issue_stage(
    uint32_t sbase,
    const __nv_bfloat16* gAh, const __nv_bfloat16* gAl, size_t strideA,
    const __nv_bfloat16* gBh, const __nv_bfloat16* gBl, size_t strideB,
    int k0, int tid)
{
    const int r = tid >> 2;
    const int q = tid & 3;
    const uint32_t so = (uint32_t)((r * LDA + q * 8) * 2);
    const uint32_t so2 = (uint32_t)(((r + 64) * LDA + q * 8) * 2);
    const size_t go = (size_t)r * strideA + k0 + q * 8;
    const size_t go2 = (size_t)(r + 64) * strideA + k0 + q * 8;
    const size_t gb = (size_t)r * strideB + k0 + q * 8;
    const size_t gb2 = (size_t)(r + 64) * strideB + k0 + q * 8;

    cp_async16(sbase + so, gAh + go);
    cp_async16(sbase + so2, gAh + go2);
    cp_async16(sbase + TILE_E * 2 + so, gAl + go);
    cp_async16(sbase + TILE_E * 2 + so2, gAl + go2);
    cp_async16(sbase + 2 * TILE_E * 2 + so, gBh + gb);
    cp_async16(sbase + 2 * TILE_E * 2 + so2, gBh + gb2);
    cp_async16(sbase + 3 * TILE_E * 2 + so, gBl + gb);
    cp_async16(sbase + 3 * TILE_E * 2 + so2, gBl + gb2);
}

__device__ __forceinline__ void mma_mainloop(
    const __nv_bfloat16* __restrict__ gAh, const __nv_bfloat16* __restrict__ gAl,
    size_t strideA,
    const __nv_bfloat16* __restrict__ gBh, const __nv_bfloat16* __restrict__ gBl,
    size_t strideB,
    int KTOT, char* smem, float acc[2][8][4])
{
    const int tid = threadIdx.x;
    const int lane = tid & 31, wid = tid >> 5;
    const int wm = (wid & 3) * 32;
    const int wn = (wid >> 2) * 64;

    const uint32_t sb = smem_u32(smem);

    const int a_row = lane & 15;
    const int a_col = (lane >> 4) * 8;
    const int b_row = (lane & 7) + (lane >> 4) * 8;
    const int b_col = ((lane >> 3) & 1) * 8;

    const int iters = KTOT / BK;

    issue_stage(sb, gAh, gAl, strideA, gBh, gBl, strideB, 0, tid);
    cp_commit();

    for (int it = 0; it < iters; it++) {
        if (it + 1 < iters) {
            issue_stage(sb + ((it + 1) & 1) * STAGE_E * 2,
                        gAh, gAl, strideA, gBh, gBl, strideB, (it + 1) * BK, tid);
            cp_commit();
            cp_wait1();
        } else {
            cp_wait0();
        }
        __syncthreads();

        const uint32_t st = sb + (it & 1) * STAGE_E * 2;
#pragma unroll
        for (int kk = 0; kk < BK; kk += 16) {
            uint32_t ah[2][4], al[2][4];
#pragma unroll
            for (int mt = 0; mt < 2; mt++) {
                uint32_t ra = st + (uint32_t)(((wm + mt * 16 + a_row) * LDA + kk + a_col) * 2);
                ldsm_x4(ah[mt], ra);
                ldsm_x4(al[mt], ra + TILE_E * 2);
            }
#pragma unroll
            for (int g = 0; g < 4; g++) {
                uint32_t bh[4], bl[4];
                uint32_t rb = st + 2 * TILE_E * 2 +
                              (uint32_t)(((wn + g * 16 + b_row) * LDA + kk + b_col) * 2);
                ldsm_x4(bh, rb);
                ldsm_x4(bl, rb + TILE_E * 2);
#pragma unroll
                for (int half = 0; half < 2; half++) {
                    const int u = half * 2;
                    const int nt = g * 2 + half;
#pragma unroll
                    for (int mt = 0; mt < 2; mt++) {
                        mma_bf16(acc[mt][nt], ah[mt], &bh[u]);
                        mma_bf16(acc[mt][nt], ah[mt], &bl[u]);
                        mma_bf16(acc[mt][nt], al[mt], &bh[u]);
                    }
                }
            }
        }
        __syncthreads();
    }
}

// ===========================================================================
// Projection GEMM: out[z][m][n] = sum_c W[m][c] * Xt[z][n][c] (+ bias)
// outF fp32, or bf16 hi/lo split outputs. grid (N/128, M/128, B)
// ===========================================================================
__global__ void __launch_bounds__(256) proj_mma_kernel(
    const __nv_bfloat16* __restrict__ Wh, const __nv_bfloat16* __restrict__ Wl,
    const __nv_bfloat16* __restrict__ Xh, const __nv_bfloat16* __restrict__ Xl,
    const float* __restrict__ bias,
    float* __restrict__ outF,
    __nv_bfloat16* __restrict__ outH, __nv_bfloat16* __restrict__ outL,
    int M)
{
    extern __shared__ char smem[];
    const int z = blockIdx.z;
    const int m0 = blockIdx.y * BM, n0 = blockIdx.x * BN;

    float acc[2][8][4] = {};
    mma_mainloop(Wh + (size_t)m0 * CC, Wl + (size_t)m0 * CC, CC,
                 Xh + ((size_t)z * NN_ + n0) * CC, Xl + ((size_t)z * NN_ + n0) * CC, CC,
                 CC, smem, acc);

    const int lane = threadIdx.x & 31, wid = threadIdx.x >> 5;
    const int wm = (wid & 3) * 32, wn = (wid >> 2) * 64;
#pragma unroll
    for (int mt = 0; mt < 2; mt++)
#pragma unroll
        for (int nt = 0; nt < 8; nt++) {
            int m = m0 + wm + mt * 16 + (lane >> 2);
            int n = n0 + wn + nt * 8 + 2 * (lane & 3);
            float b0 = bias ? bias[m] : 0.0f;
            float b1 = bias ? bias[m + 8] : 0.0f;
            float v00 = acc[mt][nt][0] + b0, v01 = acc[mt][nt][1] + b0;
            float v10 = acc[mt][nt][2] + b1, v11 = acc[mt][nt][3] + b1;
            if (outF) {
                *reinterpret_cast<float2*>(&outF[((size_t)z * M + m) * NN_ + n]) =
                    make_float2(v00, v01);
                *reinterpret_cast<float2*>(&outF[((size_t)z * M + m + 8) * NN_ + n]) =
                    make_float2(v10, v11);
            } else {
                __nv_bfloat16 h00 = __float2bfloat16(v00), h01 = __float2bfloat16(v01);
                __nv_bfloat16 h10 = __float2bfloat16(v10), h11 = __float2bfloat16(v11);
                __nv_bfloat162 hp0; hp0.x = h00; hp0.y = h01;
                __nv_bfloat162 hp1; hp1.x = h10; hp1.y = h11;
                __nv_bfloat162 lp0;
                lp0.x = __float2bfloat16(v00 - __bfloat162float(h00));
                lp0.y = __float2bfloat16(v01 - __bfloat162float(h01));
                __nv_bfloat162 lp1;
                lp1.x = __float2bfloat16(v10 - __bfloat162float(h10));
                lp1.y = __float2bfloat16(v11 - __bfloat162float(h11));
                *reinterpret_cast<__nv_bfloat162*>(&outH[((size_t)z * M + m) * NN_ + n]) = hp0;
                *reinterpret_cast<__nv_bfloat162*>(&outH[((size_t)z * M + m + 8) * NN_ + n]) = hp1;
                *reinterpret_cast<__nv_bfloat162*>(&outL[((size_t)z * M + m) * NN_ + n]) = lp0;
                *reinterpret_cast<__nv_bfloat162*>(&outL[((size_t)z * M + m + 8) * NN_ + n]) = lp1;
            }
        }
}

// ===========================================================================
// attn_s: S[z][i][j] = sum_d Q[d][i] K[d][j], operands k-major (d rows).
// Tiles [32 k][128 cols], trans ldmatrix. grid (8 j, 8 i, 32 z)
// ===========================================================================
__device__ __forceinline__ void issue_stage_kt(
    uint32_t sbase,
    const __nv_bfloat16* gAh, const __nv_bfloat16* gAl,
    const __nv_bfloat16* gBh, const __nv_bfloat16* gBl,
    int k0, int tid)
{
    const int r = tid >> 4;   // 0..15
    const int c = tid & 15;   // 16B chunk within 256B row
#pragma unroll
    for (int p = 0; p < 2; p++) {
        const int row = r + p * 16;
        const uint32_t so = (uint32_t)((row * LDB_KT + c * 8) * 2);
        const size_t go = (size_t)(k0 + row) * NN_ + c * 8;
        cp_async16(sbase + so, gAh + go);
        cp_async16(sbase + TILE_KT * 2 + so, gAl + go);
        cp_async16(sbase + 2 * TILE_KT * 2 + so, gBh + go);
        cp_async16(sbase + 3 * TILE_KT * 2 + so, gBl + go);
    }
}

__global__ void __launch_bounds__(256) attn_s_kernel(
    const __nv_bfloat16* __restrict__ Qh, const __nv_bfloat16* __restrict__ Ql,
    const __nv_bfloat16* __restrict__ Kh, const __nv_bfloat16* __restrict__ Kl,
    float* __restrict__ S)
{
    extern __shared__ char smem[];
    const int tid = threadIdx.x;
    const int lane = tid & 31, wid = tid >> 5;
    const int z = blockIdx.z, b = z >> 3, h = z & 7;
    const int i0 = blockIdx.y * BM, j0 = blockIdx.x * BN;
    const int wm = (wid & 3) * 32;
    const int wn = (wid >> 2) * 64;

    const __nv_bfloat16* gAh = Qh + (size_t)(b * HD + h * DD) * NN_ + i0;
    const __nv_bfloat16* gAl = Ql + (size_t)(b * HD + h * DD) * NN_ + i0;
    const __nv_bfloat16* gBh = Kh + (size_t)(b * HD + h * DD) * NN_ + j0;
    const __nv_bfloat16* gBl = Kl + (size_t)(b * HD + h * DD) * NN_ + j0;

    const uint32_t sb = smem_u32(smem);

    // trans-ldsm lane coords
    const int lr = lane & 7, lg = lane >> 3;
    // A: row = kk + lr + ((lg>>1)&1)*8 ; col = mbase + (lg&1)*8
    const int a_roff = lr + ((lg >> 1) & 1) * 8;
    const int a_coff = (lg & 1) * 8;
    // B: row = kk + lr + (lg&1)*8 ; col = nbase + ((lg>>1)&1)*8
    const int b_roff = lr + (lg & 1) * 8;
    const int b_coff = ((lg >> 1) & 1) * 8;

    float acc[2][8][4] = {};

    const int iters = DD / BK;   // 8
    issue_stage_kt(sb, gAh, gAl, gBh, gBl, 0, tid);
    cp_commit();

    for (int it = 0; it < iters; it++) {
        if (it + 1 < iters) {
            issue_stage_kt(sb + ((it + 1) & 1) * STAGE_KT * 2,
                           gAh, gAl, gBh, gBl, (it + 1) * BK, tid);
            cp_commit();
            cp_wait1();
        } else {
            cp_wait0();
        }
        __syncthreads();

        const uint32_t st = sb + (it & 1) * STAGE_KT * 2;
#pragma unroll
        for (int kk = 0; kk < BK; kk += 16) {
            uint32_t ah[2][4], al[2][4];
#pragma unroll
            for (int mt = 0; mt < 2; mt++) {
                uint32_t ra = st + (uint32_t)(((kk + a_roff) * LDB_KT +
                                              wm + mt * 16 + a_coff) * 2);
                ldsm_x4_t(ah[mt], ra);
                ldsm_x4_t(al[mt], ra + TILE_KT * 2);
            }
#pragma unroll
            for (int g = 0; g < 4; g++) {
                uint32_t bh[4], bl[4];
                uint32_t rb = st + 2 * TILE_KT * 2 +
                              (uint32_t)(((kk + b_roff) * LDB_KT +
                                          wn + g * 16 + b_coff) * 2);
                ldsm_x4_t(bh, rb);
                ldsm_x4_t(bl, rb + TILE_KT * 2);
#pragma unroll
                for (int half = 0; half < 2; half++) {
                    const int u = half * 2;
                    const int nt = g * 2 + half;
#pragma unroll
                    for (int mt = 0; mt < 2; mt++) {
                        mma_bf16(acc[mt][nt], ah[mt], &bh[u]);
                        mma_bf16(acc[mt][nt], ah[mt], &bl[u]);
                        mma_bf16(acc[mt][nt], al[mt], &bh[u]);
                    }
                }
            }
        }
        __syncthreads();
    }

#pragma unroll
    for (int mt = 0; mt < 2; mt++)
#pragma unroll
        for (int nt = 0; nt < 8; nt++) {
            int i = i0 + wm + mt * 16 + (lane >> 2);
            int j = j0 + wn + nt * 8 + 2 * (lane & 3);
            float* p0 = &S[((size_t)z * NN_ + i) * NN_ + j];
            float* p1 = &S[((size_t)z * NN_ + i + 8) * NN_ + j];
            *reinterpret_cast<float2*>(p0) = make_float2(acc[mt][nt][0], acc[mt][nt][1]);
            *reinterpret_cast<float2*>(p1) = make_float2(acc[mt][nt][2], acc[mt][nt][3]);
        }
}

// ===========================================================================
// attn_o: O[i][d] = sum_j P[i][j] V[d][j] + fused epilogue. grid (2 d, 8 i, 32 z)
// ===========================================================================
__global__ void __launch_bounds__(256) attn_o_kernel(
    const __nv_bfloat16* __restrict__ Ph, const __nv_bfloat16* __restrict__ Pl,
    const __nv_bfloat16* __restrict__ Vh, const __nv_bfloat16* __restrict__ Vl,
    const float* __restrict__ YP, const float* __restrict__ gamma,
    float* __restrict__ out)
{
    extern __shared__ char smem[];
    const int z = blockIdx.z, b = z >> 3, h = z & 7;
    const int i0 = blockIdx.y * BM, d0 = blockIdx.x * BN;

    float acc[2][8][4] = {};
    mma_mainloop(Ph + ((size_t)z * NN_ + i0) * NN_, Pl + ((size_t)z * NN_ + i0) * NN_, NN_,
                 Vh + ((size_t)b * HD + h * DD + d0) * NN_,
                 Vl + ((size_t)b * HD + h * DD + d0) * NN_, NN_,
                 NN_, smem, acc);

    const int lane = threadIdx.x & 31, wid = threadIdx.x >> 5;
    const int wm = (wid & 3) * 32, wn = (wid >> 2) * 64;
    const float g = gamma[h];
    const float inv1pg = 1.0f / (1.0f + g);

#pragma unroll
    for (int mt = 0; mt < 2; mt++)
#pragma unroll
        for (int nt = 0; nt < 8; nt++) {
            int i = i0 + wm + mt * 16 + (lane >> 2);
            int d = d0 + wn + nt * 8 + 2 * (lane & 3);
#pragma unroll
            for (int u = 0; u < 4; u++) {
                int dd = d + (u & 1);
                int ii = i + (u >> 1) * 8;
                float yp = YP[((size_t)b * CC + dd) * NN_ + ii];
                out[((size_t)b * HD + h * DD + dd) * NN_ + ii] =
                    (g * acc[mt][nt][u] + yp) * inv1pg;
            }
        }
}

// ===========================================================================
// Transpose+split both inputs: [B][C][N] fp32 -> [B][N][C] bf16 hi/lo
// grid (N/32, C/32, 2*B) ; z<BB -> x, else y
// ===========================================================================
__global__ void __launch_bounds__(256) transpose_split_in_kernel(
    const float* __restrict__ x, const float* __restrict__ y,
    __nv_bfloat16* __restrict__ xh, __nv_bfloat16* __restrict__ xl,
    __nv_bfloat16* __restrict__ yh, __nv_bfloat16* __restrict__ yl)
{
    __shared__ float t[32][33];
    int bz = blockIdx.z;
    const float* in;
    __nv_bfloat16 *oh, *ol;
    if (bz < BB) { in = x; oh = xh; ol = xl; }
    else { bz -= BB; in = y; oh = yh; ol = yl; }
    const int n0 = blockIdx.x * 32, c0 = blockIdx.y * 32;
    const int tx = threadIdx.x, ty = threadIdx.y;
    for (int r = ty; r < 32; r += 8)
        t[r][tx] = in[((size_t)bz * CC + c0 + r) * NN_ + n0 + tx];
    __syncthreads();
    for (int r = ty; r < 32; r += 8) {
        float v = t[tx][r];
        __nv_bfloat16 hi = __float2bfloat16(v);
        size_t o = ((size_t)bz * NN_ + n0 + r) * CC + c0 + tx;
        oh[o] = hi;
        ol[o] = __float2bfloat16(v - __bfloat162float(hi));
    }
}

// ===========================================================================
// Split all 4 weight matrices in one launch. grid (2048, 4)
// ===========================================================================
__global__ void __launch_bounds__(256) split_weights_kernel(
    const float* __restrict__ Wq, const float* __restrict__ Wk,
    const float* __restrict__ Wv, const float* __restrict__ Wp,
    __nv_bfloat16* __restrict__ Wqh, __nv_bfloat16* __restrict__ Wql,
    __nv_bfloat16* __restrict__ Wkh, __nv_bfloat16* __restrict__ Wkl,
    __nv_bfloat16* __restrict__ Wvh, __nv_bfloat16* __restrict__ Wvl,
    __nv_bfloat16* __restrict__ Wph, __nv_bfloat16* __restrict__ Wpl)
{
    const float* in;
    __nv_bfloat16 *oh, *ol;
    int n;
    switch (blockIdx.y) {
        case 0: in = Wq; oh = Wqh; ol = Wql; n = HD * CC; break;
        case 1: in = Wk; oh = Wkh; ol = Wkl; n = HD * CC; break;
        case 2: in = Wv; oh = Wvh; ol = Wvl; n = HD * CC; break;
        default: in = Wp; oh = Wph; ol = Wpl; n = CC * CC; break;
    }
    int i = blockIdx.x * 256 + threadIdx.x;
    if (i < n) {
        float v = in[i];
        __nv_bfloat16 hi = __float2bfloat16(v);
        oh[i] = hi;
        ol[i] = __float2bfloat16(v - __bfloat162float(hi));
    }
}

// ===========================================================================
// Row softmax over keys, emit bf16 hi/lo
// ===========================================================================
__global__ void __launch_bounds__(256) softmax_kernel(
    const float* __restrict__ S,
    __nv_bfloat16* __restrict__ Ph, __nv_bfloat16* __restrict__ Pl)
{
    __shared__ float red[256];
    const size_t row = blockIdx.x;
    const float* r = S + row * NN_;
    const int tid = threadIdx.x;

    float v[4];
    float mx = -INFINITY;
#pragma unroll
    for (int j = 0; j < 4; j++) { v[j] = r[tid + j * 256]; mx = fmaxf(mx, v[j]); }
    red[tid] = mx;
    __syncthreads();
    for (int s = 128; s > 0; s >>= 1) {
        if (tid < s) red[tid] = fmaxf(red[tid], red[tid + s]);
        __syncthreads();
    }
    mx = red[0];
    __syncthreads();

    float sum = 0.0f;
#pragma unroll
    for (int j = 0; j < 4; j++) { v[j] = __expf(v[j] - mx); sum += v[j]; }
    red[tid] = sum;
    __syncthreads();
    for (int s = 128; s > 0; s >>= 1) {
        if (tid < s) red[tid] += red[tid + s];
        __syncthreads();
    }
    float inv = 1.0f / red[0];

#pragma unroll
    for (int j = 0; j < 4; j++) {
        float p = v[j] * inv;
        __nv_bfloat16 hi = __float2bfloat16(p);
        size_t o = row * NN_ + tid + j * 256;
        Ph[o] = hi;
        Pl[o] = __float2bfloat16(p - __bfloat162float(hi));
    }
}

// ---------------------------------------------------------------------------
extern "C" void kernel_launch(void* const* d_in, const int* in_sizes, int n_in,
                              void* d_out, int out_size)
{
    const float* x     = (const float*)d_in[0];
    const float* y     = (const float*)d_in[1];
    const float* Wq    = (const float*)d_in[2];
    const float* bq    = (const float*)d_in[3];
    const float* Wk    = (const float*)d_in[4];
    const float* bk    = (const float*)d_in[5];
    const float* Wv    = (const float*)d_in[6];
    const float* bv    = (const float*)d_in[7];
    const float* Wp    = (const float*)d_in[8];
    const float* gamma = (const float*)d_in[9];
    float* out = (float*)d_out;

    float *YP, *S;
    __nv_bfloat16 *Wqh, *Wql, *Wkh, *Wkl, *Wvh, *Wvl, *Wph, *Wpl;
    __nv_bfloat16 *Xth, *Xtl, *Yth, *Ytl;
    __nv_bfloat16 *Qh, *Ql, *Kh, *Kl, *Vh, *Vl, *Ph, *Pl;
    cudaGetSymbolAddress((void**)&YP,  g_YP);
    cudaGetSymbolAddress((void**)&S,   g_S);
    cudaGetSymbolAddress((void**)&Wqh, g_Wqh);
    cudaGetSymbolAddress((void**)&Wql, g_Wql);
    cudaGetSymbolAddress((void**)&Wkh, g_Wkh);
    cudaGetSymbolAddress((void**)&Wkl, g_Wkl);
    cudaGetSymbolAddress((void**)&Wvh, g_Wvh);
    cudaGetSymbolAddress((void**)&Wvl, g_Wvl);
    cudaGetSymbolAddress((void**)&Wph, g_Wph);
    cudaGetSymbolAddress((void**)&Wpl, g_Wpl);
    cudaGetSymbolAddress((void**)&Xth, g_Xth);
    cudaGetSymbolAddress((void**)&Xtl, g_Xtl);
    cudaGetSymbolAddress((void**)&Yth, g_Yth);
    cudaGetSymbolAddress((void**)&Ytl, g_Ytl);
    cudaGetSymbolAddress((void**)&Qh,  g_Qh);
    cudaGetSymbolAddress((void**)&Ql,  g_Ql);
    cudaGetSymbolAddress((void**)&Kh,  g_Kh);
    cudaGetSymbolAddress((void**)&Kl,  g_Kl);
    cudaGetSymbolAddress((void**)&Vh,  g_Vh);
    cudaGetSymbolAddress((void**)&Vl,  g_Vl);
    cudaGetSymbolAddress((void**)&Ph,  g_Ph);
    cudaGetSymbolAddress((void**)&Pl,  g_Pl);

    cudaFuncSetAttribute(proj_mma_kernel, cudaFuncAttributeMaxDynamicSharedMemorySize, SMEM_BYTES);
    cudaFuncSetAttribute(attn_s_kernel, cudaFuncAttributeMaxDynamicSharedMemorySize, SMEM_S_BYTES);
    cudaFuncSetAttribute(attn_o_kernel, cudaFuncAttributeMaxDynamicSharedMemorySize, SMEM_BYTES);

    dim3 t(256);

    // Weight splits (1 launch)
    split_weights_kernel<<<dim3((HD * CC + 255) / 256, 4), t>>>(
        Wq, Wk, Wv, Wp, Wqh, Wql, Wkh, Wkl, Wvh, Wvl, Wph, Wpl);

    // Input transposes+splits (1 launch): [B][C][N] -> [B][N][C]
    transpose_split_in_kernel<<<dim3(32, 8, 2 * BB), dim3(32, 8)>>>(
        x, y, Xth, Xtl, Yth, Ytl);

    // Projections (HMMA), all bf16 hi/lo except YP:
    proj_mma_kernel<<<dim3(8, 16, BB), t, SMEM_BYTES>>>(
        Wqh, Wql, Xth, Xtl, bq, nullptr, Qh, Ql, HD);
    proj_mma_kernel<<<dim3(8, 16, BB), t, SMEM_BYTES>>>(
        Wkh, Wkl, Xth, Xtl, bk, nullptr, Kh, Kl, HD);
    proj_mma_kernel<<<dim3(8, 16, BB), t, SMEM_BYTES>>>(
        Wvh, Wvl, Yth, Ytl, bv, nullptr, Vh, Vl, HD);
    proj_mma_kernel<<<dim3(8, 2, BB), t, SMEM_BYTES>>>(
        Wph, Wpl, Yth, Ytl, nullptr, YP, nullptr, nullptr, CC);

    // S = Q^T K directly from d-major operands (trans ldmatrix)
    attn_s_kernel<<<dim3(8, 8, ZZ), t, SMEM_S_BYTES>>>(Qh, Ql, Kh, Kl, S);

    // softmax -> P hi/lo
    softmax_kernel<<<ZZ * NN_, t>>>(S, Ph, Pl);

    // O = P V^T + epilogue
    attn_o_kernel<<<dim3(2, 8, ZZ), t, SMEM_BYTES>>>(Ph, Pl, Vh, Vl, YP, gamma, out);
}